// round 11
// baseline (speedup 1.0000x reference)
#include <cuda_runtime.h>
#include <cstdint>

#define NN   50000
#define NHE  10000
#define NE   800000
#define NI   800000
#define HID  128
#define OUTC 64

// ---------------- device scratch ----------------
__device__ __align__(16) float g_A[NN * HID];
__device__ __align__(16) float g_B[NN * HID];
__device__ __align__(16) float g_X1[NN * HID];
__device__ __align__(16) float g_X2[NN * HID];
__device__ __align__(16) float g_T[NN * HID];
__device__ __align__(16) float g_M[NHE * HID];
// packed tf32 weights: per w, [chunk(2)][kt(8)][n(128)][t(4)] float4 = (b0h,b1h,b0l,b1l)
__device__ __align__(16) float4 g_Wp[9 * 8192];
__device__ __align__(16) float g_bsum1[HID];
__device__ __align__(16) float g_bsum2[HID];
__device__ __align__(16) float g_Binv[NHE];
__device__ __align__(16) float g_Dinv[NN];

__device__ int g_idx64;
__device__ __align__(16) int g_deg_he[NHE];
__device__ __align__(16) int g_off_he[NHE + 1];
__device__ __align__(16) int g_cur_he[NHE];
__device__ __align__(16) int g_deg_nh[NN];
__device__ __align__(16) int g_off_nh[NN + 1];
__device__ __align__(16) int g_cur_nh[NN];
__device__ __align__(16) int g_deg_nd[NN];
__device__ __align__(16) int g_off_nd[NN + 1];
__device__ __align__(16) int g_cur_nd[NN];
__device__ int g_list_he[NI];
__device__ int g_list_nh[NI];
__device__ int g_list_nd[NE];

__device__ __forceinline__ float leakyf(float x) { return x >= 0.f ? x : 0.01f * x; }
__device__ __forceinline__ int clampi(int v, int hi) { return v < 0 ? 0 : (v >= hi ? hi - 1 : v); }

__device__ __forceinline__ int idxat(const int* __restrict__ a, int pos) {
    return g_idx64 ? a[2 * (long long)pos] : a[pos];
}

__device__ __forceinline__ const float* srcbuf(int id, const float* ext) {
    switch (id) {
        case 0: return g_A;
        case 1: return g_B;
        case 2: return g_X1;
        case 3: return g_X2;
        case 4: return g_T;
        default: return ext;
    }
}
__device__ __forceinline__ float* dstbuf(int id, float* ext) {
    switch (id) {
        case 0: return g_A;
        case 1: return g_B;
        case 2: return g_X1;
        case 3: return g_X2;
        case 4: return g_T;
        default: return ext;
    }
}

__device__ __forceinline__ uint32_t f2tf(float x) {
    uint32_t r; asm("cvt.rna.tf32.f32 %0, %1;" : "=r"(r) : "f"(x)); return r;
}

__device__ __forceinline__ void mma8(float c[4], uint32_t a0, uint32_t a1, uint32_t a2, uint32_t a3,
                                     uint32_t b0, uint32_t b1) {
    asm volatile("mma.sync.aligned.m16n8k8.row.col.f32.tf32.tf32.f32 "
                 "{%0,%1,%2,%3},{%4,%5,%6,%7},{%8,%9},{%0,%1,%2,%3};"
                 : "+f"(c[0]), "+f"(c[1]), "+f"(c[2]), "+f"(c[3])
                 : "r"(a0), "r"(a1), "r"(a2), "r"(a3), "r"(b0), "r"(b1));
}

// ---------------- index dtype detect ----------------
__global__ void detect_kernel(const int* __restrict__ he) {
    __shared__ int any;
    if (threadIdx.x == 0) any = 0;
    __syncthreads();
    if (he[2 * threadIdx.x + 1] != 0) atomicOr(&any, 1);
    __syncthreads();
    if (threadIdx.x == 0) g_idx64 = (any == 0) ? 1 : 0;
}

// ---------------- weight prep: transpose + tf32 hi/lo decompose into packed fragments ----
struct WList { const float* a[9]; const float* b[9]; int ncols[9]; };

__global__ void decompose_kernel(WList wl) {
    int w = blockIdx.y;
    int i = blockIdx.x * blockDim.x + threadIdx.x;   // 0..8191
    int t = i & 3, n = (i >> 2) & 127, kt = (i >> 9) & 7, c = i >> 12;
    int NC = wl.ncols[w];
    int k1 = c * 64 + kt * 8 + t, k2 = k1 + 4;
    float v1 = 0.f, v2 = 0.f;
    if (n < NC) {
        v1 = wl.a[w][k1 * NC + n];
        v2 = wl.a[w][k2 * NC + n];
        if (wl.b[w]) { v1 += wl.b[w][k1 * NC + n]; v2 += wl.b[w][k2 * NC + n]; }
    }
    float h1 = __uint_as_float(f2tf(v1));
    float h2 = __uint_as_float(f2tf(v2));
    g_Wp[w * 8192 + i] = make_float4(h1, h2, v1 - h1, v2 - h2);
}

__global__ void bias_combine_kernel(const float* __restrict__ a1, const float* __restrict__ b1,
                                    const float* __restrict__ a2, const float* __restrict__ b2) {
    int i = threadIdx.x;
    if (i < HID) { g_bsum1[i] = a1[i] + b1[i]; g_bsum2[i] = a2[i] + b2[i]; }
}

// ---------------- CSR build ----------------
__global__ void zero_deg_kernel() {
    int i = blockIdx.x * blockDim.x + threadIdx.x;
    if (i < NHE) g_deg_he[i] = 0;
    if (i < NN) { g_deg_nh[i] = 0; g_deg_nd[i] = 0; }
}

__global__ void count_kernel(const int* __restrict__ he, const int* __restrict__ ed) {
    int i = blockIdx.x * blockDim.x + threadIdx.x;
    if (i < NI) {
        atomicAdd(&g_deg_nh[clampi(idxat(he, i), NN)], 1);
        atomicAdd(&g_deg_he[clampi(idxat(he, NI + i), NHE)], 1);
    }
    if (i < NE) {
        atomicAdd(&g_deg_nd[clampi(idxat(ed, NE + i), NN)], 1);
    }
}

// fast two-level shuffle scan; 3 independent scans, blockIdx.x = which
__global__ void scan_kernel() {
    int which = blockIdx.x;
    const int* __restrict__ deg; int n; int* __restrict__ off; int* __restrict__ cur;
    float* __restrict__ inv;
    if (which == 0)      { deg = g_deg_he; n = NHE; off = g_off_he; cur = g_cur_he; inv = g_Binv; }
    else if (which == 1) { deg = g_deg_nh; n = NN;  off = g_off_nh; cur = g_cur_nh; inv = g_Dinv; }
    else                 { deg = g_deg_nd; n = NN;  off = g_off_nd; cur = g_cur_nd; inv = 0; }

    __shared__ int wsum[32];
    __shared__ int s_tot;
    __shared__ int s_run;
    int tid = threadIdx.x;
    int lane = tid & 31, wid = tid >> 5;
    if (tid == 0) s_run = 0;
    __syncthreads();

    int nt = (n + 4095) / 4096;
    for (int t = 0; t < nt; ++t) {
        int base = t * 4096 + tid * 4;
        int d0 = 0, d1 = 0, d2 = 0, d3 = 0;
        if (base + 3 < n) {
            int4 v = *(const int4*)&deg[base];
            d0 = v.x; d1 = v.y; d2 = v.z; d3 = v.w;
        } else {
            if (base + 0 < n) d0 = deg[base + 0];
            if (base + 1 < n) d1 = deg[base + 1];
            if (base + 2 < n) d2 = deg[base + 2];
            if (base + 3 < n) d3 = deg[base + 3];
        }
        int s = d0 + d1 + d2 + d3;
        int incl = s;
#pragma unroll
        for (int o = 1; o < 32; o <<= 1) {
            int v = __shfl_up_sync(0xFFFFFFFFu, incl, o);
            if (lane >= o) incl += v;
        }
        if (lane == 31) wsum[wid] = incl;
        __syncthreads();
        if (wid == 0) {
            int ws = wsum[lane];
            int wincl = ws;
#pragma unroll
            for (int o = 1; o < 32; o <<= 1) {
                int v = __shfl_up_sync(0xFFFFFFFFu, wincl, o);
                if (lane >= o) wincl += v;
            }
            wsum[lane] = wincl - ws;
            if (lane == 31) s_tot = wincl;
        }
        __syncthreads();
        int excl = s_run + wsum[wid] + (incl - s);
        int o0 = excl, o1 = o0 + d0, o2 = o1 + d1, o3 = o2 + d2;
        if (base + 3 < n) {
            *(int4*)&off[base] = make_int4(o0, o1, o2, o3);
            *(int4*)&cur[base] = make_int4(o0, o1, o2, o3);
            if (inv) {
                float4 f;
                f.x = d0 ? 1.0f / (float)d0 : 0.0f;
                f.y = d1 ? 1.0f / (float)d1 : 0.0f;
                f.z = d2 ? 1.0f / (float)d2 : 0.0f;
                f.w = d3 ? 1.0f / (float)d3 : 0.0f;
                *(float4*)&inv[base] = f;
            }
        } else {
            if (base + 0 < n) { off[base + 0] = o0; cur[base + 0] = o0; if (inv) inv[base + 0] = d0 ? 1.0f / (float)d0 : 0.0f; }
            if (base + 1 < n) { off[base + 1] = o1; cur[base + 1] = o1; if (inv) inv[base + 1] = d1 ? 1.0f / (float)d1 : 0.0f; }
            if (base + 2 < n) { off[base + 2] = o2; cur[base + 2] = o2; if (inv) inv[base + 2] = d2 ? 1.0f / (float)d2 : 0.0f; }
            if (base + 3 < n) { off[base + 3] = o3; cur[base + 3] = o3; if (inv) inv[base + 3] = d3 ? 1.0f / (float)d3 : 0.0f; }
        }
        __syncthreads();
        if (tid == 0) s_run += s_tot;
        __syncthreads();
    }
    if (tid == 0) off[n] = s_run;
}

__global__ void fill_kernel(const int* __restrict__ he, const int* __restrict__ ed) {
    int i = blockIdx.x * blockDim.x + threadIdx.x;
    if (i < NI) {
        int n = clampi(idxat(he, i), NN);
        int h = clampi(idxat(he, NI + i), NHE);
        g_list_he[atomicAdd(&g_cur_he[h], 1)] = n;
        g_list_nh[atomicAdd(&g_cur_nh[n], 1)] = h;
    }
    if (i < NE) {
        int s = clampi(idxat(ed, i), NN);
        int d = clampi(idxat(ed, NE + i), NN);
        g_list_nd[atomicAdd(&g_cur_nd[d], 1)] = s;
    }
}

// ---------------- gather segment-sums (1 warp per output row, 8-deep MLP) ----------------
#define GATHER_BODY(listarr, srcptr) \
    float ax = 0.f, ay = 0.f, az = 0.f, aw = 0.f; \
    int i = beg; \
    for (; i + 8 <= end; i += 8) { \
        int n0 = listarr[i], n1 = listarr[i + 1], n2 = listarr[i + 2], n3 = listarr[i + 3]; \
        int n4 = listarr[i + 4], n5 = listarr[i + 5], n6 = listarr[i + 6], n7 = listarr[i + 7]; \
        float4 v0 = srcptr[n0 * 32 + lane]; \
        float4 v1 = srcptr[n1 * 32 + lane]; \
        float4 v2 = srcptr[n2 * 32 + lane]; \
        float4 v3 = srcptr[n3 * 32 + lane]; \
        float4 v4 = srcptr[n4 * 32 + lane]; \
        float4 v5 = srcptr[n5 * 32 + lane]; \
        float4 v6 = srcptr[n6 * 32 + lane]; \
        float4 v7 = srcptr[n7 * 32 + lane]; \
        ax += ((v0.x + v1.x) + (v2.x + v3.x)) + ((v4.x + v5.x) + (v6.x + v7.x)); \
        ay += ((v0.y + v1.y) + (v2.y + v3.y)) + ((v4.y + v5.y) + (v6.y + v7.y)); \
        az += ((v0.z + v1.z) + (v2.z + v3.z)) + ((v4.z + v5.z) + (v6.z + v7.z)); \
        aw += ((v0.w + v1.w) + (v2.w + v3.w)) + ((v4.w + v5.w) + (v6.w + v7.w)); \
    } \
    for (; i < end; ++i) { \
        int nn_ = listarr[i]; \
        float4 v = srcptr[nn_ * 32 + lane]; \
        ax += v.x; ay += v.y; az += v.z; aw += v.w; \
    }

__global__ void gather_he_kernel() {
    int row = (blockIdx.x * blockDim.x + threadIdx.x) >> 5;
    if (row >= NHE) return;
    int lane = threadIdx.x & 31;
    int beg = g_off_he[row], end = g_off_he[row + 1];
    const float4* src = (const float4*)g_A;
    GATHER_BODY(g_list_he, src)
    float b = g_Binv[row];
    ((float4*)g_M)[row * 32 + lane] = make_float4(ax * b, ay * b, az * b, aw * b);
}

__global__ void gather_node_fuse_kernel(const float4* __restrict__ hcb,
                                        const float4* __restrict__ linb,
                                        int outsel) {
    int row = (blockIdx.x * blockDim.x + threadIdx.x) >> 5;
    if (row >= NN) return;
    int lane = threadIdx.x & 31;
    int beg = g_off_nh[row], end = g_off_nh[row + 1];
    const float4* m = (const float4*)g_M;
    GATHER_BODY(g_list_nh, m)
    float dinv = g_Dinv[row];
    float4 b1 = hcb[lane];
    float4 b2 = linb[lane];
    const float4* linP = (const float4*)g_B;
    float4 l = linP[row * 32 + lane];
    float4 r;
    r.x = leakyf(ax * dinv + b1.x + b2.x + l.x);
    r.y = leakyf(ay * dinv + b1.y + b2.y + l.y);
    r.z = leakyf(az * dinv + b1.z + b2.z + l.z);
    r.w = leakyf(aw * dinv + b1.w + b2.w + l.w);
    ((float4*)dstbuf(outsel, 0))[row * 32 + lane] = r;
}

__global__ void gather_edge_kernel(int srcsel) {
    int row = (blockIdx.x * blockDim.x + threadIdx.x) >> 5;
    if (row >= NN) return;
    int lane = threadIdx.x & 31;
    int beg = g_off_nd[row], end = g_off_nd[row + 1];
    const float4* src = (const float4*)srcbuf(srcsel, 0);
    GATHER_BODY(g_list_nd, src)
    ((float4*)g_A)[row * 32 + lane] = make_float4(ax, ay, az, aw);
}

// ---------------- 3xTF32 tensor-core GEMM with packed-B fragments ----------------
// C[M x KOUT] = A[M x 128] @ W[128 x KOUT]; W prepacked in g_Wp (widx).
// If gridDim.y == 2, blockIdx.y == 1 uses widxB/cselB (independent pair in one launch).
// MODE 0: C = acc ; MODE 1: C = acc + bias_ext ; MODE 3: C = acc + bsum(bs) ;
// MODE 4: C = leaky(acc + g_T)
template <int MODE, int NT>
__global__ __launch_bounds__(256, 2)
void gemm_tf32(const float* __restrict__ Aext, float* __restrict__ Cext,
               const float* __restrict__ bias_ext, int asel, int csel, int widx,
               int bs, int M, int widxB, int cselB) {
    constexpr int KOUT = NT * 8;
    if (blockIdx.y == 1) { widx = widxB; csel = cselB; }
    const float* A = srcbuf(asel, Aext);
    float* C = dstbuf(csel, Cext);

    extern __shared__ float sm[];
    float* As = sm;                           // [128][68]
    float4* Bs4 = (float4*)(sm + 128 * 68);   // [8 kt][128 n][4 t]

    int tid = threadIdx.x;
    int lane = tid & 31, warp = tid >> 5;
    int g = lane >> 2, t = lane & 3;
    int brow = blockIdx.x * 128;
    int wr = warp * 16;

    float c[NT][4];
#pragma unroll
    for (int nt = 0; nt < NT; ++nt)
#pragma unroll
        for (int j = 0; j < 4; ++j) c[nt][j] = 0.f;

#pragma unroll
    for (int chunk = 0; chunk < 2; ++chunk) {
        int k0 = chunk * 64;
        if (chunk) __syncthreads();
        // stage A chunk [128 rows][64 k]
#pragma unroll
        for (int p = 0; p < 8; ++p) {
            int idx = p * 256 + tid;
            int r = idx >> 4, c4 = (idx & 15) * 4;
            int gr = brow + r;
            float4 v = make_float4(0.f, 0.f, 0.f, 0.f);
            if (gr < M) v = *(const float4*)&A[(size_t)gr * 128 + k0 + c4];
            *(float4*)&As[r * 68 + c4] = v;
        }
        // stage packed B chunk: 4096 float4 straight copy
        const float4* Wp = g_Wp + widx * 8192 + chunk * 4096;
#pragma unroll
        for (int p = 0; p < 16; ++p) {
            int idx = p * 256 + tid;
            Bs4[idx] = Wp[idx];
        }
        __syncthreads();

#pragma unroll
        for (int kt = 0; kt < 8; ++kt) {
            int kk = kt * 8;
            float a0 = As[(wr + g) * 68 + kk + t];
            float a1 = As[(wr + g + 8) * 68 + kk + t];
            float a2 = As[(wr + g) * 68 + kk + t + 4];
            float a3 = As[(wr + g + 8) * 68 + kk + t + 4];
            uint32_t ah0 = f2tf(a0), ah1 = f2tf(a1), ah2 = f2tf(a2), ah3 = f2tf(a3);
            uint32_t al0 = __float_as_uint(a0 - __uint_as_float(ah0));
            uint32_t al1 = __float_as_uint(a1 - __uint_as_float(ah1));
            uint32_t al2 = __float_as_uint(a2 - __uint_as_float(ah2));
            uint32_t al3 = __float_as_uint(a3 - __uint_as_float(ah3));
#pragma unroll
            for (int nt = 0; nt < NT; ++nt) {
                float4 b = Bs4[kt * 512 + (nt * 8 + g) * 4 + t];
                uint32_t b0h = __float_as_uint(b.x);
                uint32_t b1h = __float_as_uint(b.y);
                uint32_t b0l = __float_as_uint(b.z);
                uint32_t b1l = __float_as_uint(b.w);
                mma8(c[nt], ah0, ah1, ah2, ah3, b0h, b1h);
                mma8(c[nt], al0, al1, al2, al3, b0h, b1h);
                mma8(c[nt], ah0, ah1, ah2, ah3, b0l, b1l);
            }
        }
    }

    // epilogue
    const float* bsum = bs ? g_bsum2 : g_bsum1;
    int r0 = brow + wr + g;
    int r1 = r0 + 8;
#pragma unroll
    for (int nt = 0; nt < NT; ++nt) {
        int col = nt * 8 + 2 * t;
        if (r0 < M) {
            float v0 = c[nt][0], v1 = c[nt][1];
            if (MODE == 1) { v0 += bias_ext[col]; v1 += bias_ext[col + 1]; }
            if (MODE == 3) { v0 += bsum[col]; v1 += bsum[col + 1]; }
            if (MODE == 4) {
                v0 = leakyf(v0 + g_T[(size_t)r0 * 128 + col]);
                v1 = leakyf(v1 + g_T[(size_t)r0 * 128 + col + 1]);
            }
            *(float2*)&C[(size_t)r0 * KOUT + col] = make_float2(v0, v1);
        }
        if (r1 < M) {
            float v2 = c[nt][2], v3 = c[nt][3];
            if (MODE == 1) { v2 += bias_ext[col]; v3 += bias_ext[col + 1]; }
            if (MODE == 3) { v2 += bsum[col]; v3 += bsum[col + 1]; }
            if (MODE == 4) {
                v2 = leakyf(v2 + g_T[(size_t)r1 * 128 + col]);
                v3 = leakyf(v3 + g_T[(size_t)r1 * 128 + col + 1]);
            }
            *(float2*)&C[(size_t)r1 * KOUT + col] = make_float2(v2, v3);
        }
    }
}

// ---------------- launch ----------------
extern "C" void kernel_launch(void* const* d_in, const int* in_sizes, int n_in,
                              void* d_out, int out_size) {
    const float* X     = (const float*)d_in[0];
    const int* eidx    = (const int*)d_in[1];
    const int* hidx    = (const int*)d_in[2];
    const float* hc1w  = (const float*)d_in[3];
    const float* hc1b  = (const float*)d_in[4];
    const float* lin1w = (const float*)d_in[5];
    const float* lin1b = (const float*)d_in[6];
    const float* hc2w  = (const float*)d_in[7];
    const float* hc2b  = (const float*)d_in[8];
    const float* lin2w = (const float*)d_in[9];
    const float* lin2b = (const float*)d_in[10];
    const float* c1wrel  = (const float*)d_in[11];
    const float* c1brel  = (const float*)d_in[12];
    const float* c1wroot = (const float*)d_in[13];
    const float* glin1w  = (const float*)d_in[14];
    const float* glin1b  = (const float*)d_in[15];
    const float* c2wrel  = (const float*)d_in[16];
    const float* c2brel  = (const float*)d_in[17];
    const float* c2wroot = (const float*)d_in[18];
    const float* glin2w  = (const float*)d_in[19];
    const float* glin2b  = (const float*)d_in[20];
    const float* fcw = (const float*)d_in[21];
    const float* fcb = (const float*)d_in[22];

    const size_t NX = (size_t)NN * HID;
    const size_t NYsz = (size_t)NN * OUTC;
    bool full_out = ((size_t)out_size >= NX + NYsz);
    float* outX = (float*)d_out;
    float* outY = full_out ? (outX + NX) : (float*)d_out;
    int final_csel = full_out ? -1 : 3;
    int fc_asel    = full_out ? -1 : 3;
    const float* fc_Aext = full_out ? outX : (const float*)0;

    const int TPB = 256;
    const int SMEMSZ = 128 * 68 * 4 + 4096 * 16;    // 100352 B
    int gG = (NN + 127) / 128;
    int gbE   = (NE + TPB - 1) / TPB;
    int gbHEw = (NHE * 32 + TPB - 1) / TPB;
    int gbNw  = (NN * 32 + TPB - 1) / TPB;

    cudaFuncSetAttribute((const void*)gemm_tf32<0, 16>, cudaFuncAttributeMaxDynamicSharedMemorySize, SMEMSZ);
    cudaFuncSetAttribute((const void*)gemm_tf32<3, 16>, cudaFuncAttributeMaxDynamicSharedMemorySize, SMEMSZ);
    cudaFuncSetAttribute((const void*)gemm_tf32<4, 16>, cudaFuncAttributeMaxDynamicSharedMemorySize, SMEMSZ);
    cudaFuncSetAttribute((const void*)gemm_tf32<1, 8>,  cudaFuncAttributeMaxDynamicSharedMemorySize, SMEMSZ);

    // side stream + events (created once; graph capture forks/joins via events)
    static cudaStream_t s1 = 0;
    static cudaEvent_t evFork = 0, evCSR = 0, evX2 = 0, evT1 = 0, evL3 = 0, evT2 = 0;
    if (!s1) {
        cudaStreamCreate(&s1);
        cudaEventCreateWithFlags(&evFork, cudaEventDisableTiming);
        cudaEventCreateWithFlags(&evCSR,  cudaEventDisableTiming);
        cudaEventCreateWithFlags(&evX2,   cudaEventDisableTiming);
        cudaEventCreateWithFlags(&evT1,   cudaEventDisableTiming);
        cudaEventCreateWithFlags(&evL3,   cudaEventDisableTiming);
        cudaEventCreateWithFlags(&evT2,   cudaEventDisableTiming);
    }

    // ---- fork: CSR chain on s1, weight prep + L1 GEMMs on main ----
    cudaEventRecord(evFork, 0);
    cudaStreamWaitEvent(s1, evFork, 0);
    detect_kernel<<<1, 256, 0, s1>>>(hidx);
    zero_deg_kernel<<<(NN + TPB - 1) / TPB, TPB, 0, s1>>>();
    count_kernel<<<gbE, TPB, 0, s1>>>(hidx, eidx);
    scan_kernel<<<3, 1024, 0, s1>>>();
    fill_kernel<<<gbE, TPB, 0, s1>>>(hidx, eidx);
    cudaEventRecord(evCSR, s1);

    WList wl;
    wl.a[0] = hc1w;    wl.b[0] = 0;      wl.ncols[0] = 128;
    wl.a[1] = lin1w;   wl.b[1] = 0;      wl.ncols[1] = 128;
    wl.a[2] = hc2w;    wl.b[2] = 0;      wl.ncols[2] = 128;
    wl.a[3] = lin2w;   wl.b[3] = 0;      wl.ncols[3] = 128;
    wl.a[4] = c1wrel;  wl.b[4] = 0;      wl.ncols[4] = 128;
    wl.a[5] = c1wroot; wl.b[5] = glin1w; wl.ncols[5] = 128;
    wl.a[6] = c2wrel;  wl.b[6] = 0;      wl.ncols[6] = 128;
    wl.a[7] = c2wroot; wl.b[7] = glin2w; wl.ncols[7] = 128;
    wl.a[8] = fcw;     wl.b[8] = 0;      wl.ncols[8] = 64;
    decompose_kernel<<<dim3(32, 9), TPB>>>(wl);
    bias_combine_kernel<<<1, 128>>>(c1brel, glin1b, c2brel, glin2b);

    // ---- layer 1 (hypergraph): paired GEMMs in one launch ----
    gemm_tf32<0, 16><<<dim3(gG, 2), TPB, SMEMSZ>>>(X, 0, 0, -1, 0, 0, 0, NN, 1, 1);  // g_A=X@hc1w ; g_B=X@lin1w
    cudaStreamWaitEvent(0, evCSR, 0);   // gathers need CSR
    gather_he_kernel<<<gbHEw, TPB>>>();
    gather_node_fuse_kernel<<<gbNw, TPB>>>((const float4*)hc1b, (const float4*)lin1b, 2);

    // ---- layer 2 (hypergraph) ----
    gemm_tf32<0, 16><<<dim3(gG, 2), TPB, SMEMSZ>>>(0, 0, 0, 2, 0, 2, 0, NN, 3, 1);   // g_A=g_X1@hc2w ; g_B=g_X1@lin2w
    gather_he_kernel<<<gbHEw, TPB>>>();
    gather_node_fuse_kernel<<<gbNw, TPB>>>((const float4*)hc2b, (const float4*)lin2b, 3);

    // ---- layer 3 (graph): root-branch GEMM on s1 concurrent with gather_edge ----
    cudaEventRecord(evX2, 0);
    cudaStreamWaitEvent(s1, evX2, 0);
    gemm_tf32<3, 16><<<gG, TPB, SMEMSZ, s1>>>(0, 0, 0, 3, 4, 5, 0, NN, 5, 4);        // g_T = g_X2@Wc1 + bsum1
    cudaEventRecord(evT1, s1);
    gather_edge_kernel<<<gbNw, TPB>>>(3);                                            // g_A = segsum(g_X2)
    cudaStreamWaitEvent(0, evT1, 0);
    gemm_tf32<4, 16><<<gG, TPB, SMEMSZ>>>(0, 0, 0, 0, 2, 4, 0, NN, 4, 2);            // g_X1 = leaky(g_A@c1wrel + g_T)

    // ---- layer 4 (graph) ----
    cudaEventRecord(evL3, 0);
    cudaStreamWaitEvent(s1, evL3, 0);
    gemm_tf32<3, 16><<<gG, TPB, SMEMSZ, s1>>>(0, 0, 0, 2, 4, 7, 1, NN, 7, 4);        // g_T = g_X1@Wc2 + bsum2
    cudaEventRecord(evT2, s1);
    gather_edge_kernel<<<gbNw, TPB>>>(2);                                            // g_A = segsum(g_X1)
    cudaStreamWaitEvent(0, evT2, 0);
    gemm_tf32<4, 16><<<gG, TPB, SMEMSZ>>>(0, outX, 0, 0, final_csel, 6, 0, NN, 6, final_csel);  // X4

    // ---- fc head ----
    gemm_tf32<1, 8><<<gG, TPB, SMEMSZ>>>(fc_Aext, outY, fcb, fc_asel, -1, 8, 0, NN, 8, -1);
}

// round 13
// speedup vs baseline: 1.3788x; 1.3788x over previous
#include <cuda_runtime.h>
#include <cstdint>

#define NN   50000
#define NHE  10000
#define NE   800000
#define NI   800000
#define HID  128
#define OUTC 64

// ---------------- device scratch ----------------
__device__ __align__(16) float g_A[NN * HID];
__device__ __align__(16) float g_B[NN * HID];
__device__ __align__(16) float g_X1[NN * HID];
__device__ __align__(16) float g_X2[NN * HID];
__device__ __align__(16) float g_M[NHE * HID];
// packed tf32 weights: per w, [chunk(2)][kt(8)][n(128)][t(4)] float4 = (b0h,b1h,b0l,b1l)
__device__ __align__(16) float4 g_Wp[9 * 8192];
__device__ __align__(16) float g_bsum1[HID];
__device__ __align__(16) float g_bsum2[HID];
__device__ __align__(16) float g_Binv[NHE];
__device__ __align__(16) float g_Dinv[NN];

__device__ int g_idx64;
__device__ __align__(16) int g_deg_he[NHE];
__device__ __align__(16) int g_off_he[NHE + 1];
__device__ __align__(16) int g_cur_he[NHE];
__device__ __align__(16) int g_deg_nh[NN];
__device__ __align__(16) int g_off_nh[NN + 1];
__device__ __align__(16) int g_cur_nh[NN];
__device__ __align__(16) int g_deg_nd[NN];
__device__ __align__(16) int g_off_nd[NN + 1];
__device__ __align__(16) int g_cur_nd[NN];
__device__ int g_list_he[NI];
__device__ int g_list_nh[NI];
__device__ int g_list_nd[NE];

__device__ __forceinline__ float leakyf(float x) { return x >= 0.f ? x : 0.01f * x; }
__device__ __forceinline__ int clampi(int v, int hi) { return v < 0 ? 0 : (v >= hi ? hi - 1 : v); }

__device__ __forceinline__ int idxat(const int* __restrict__ a, int pos) {
    return g_idx64 ? a[2 * (long long)pos] : a[pos];
}

__device__ __forceinline__ const float* srcbuf(int id, const float* ext) {
    switch (id) {
        case 0: return g_A;
        case 1: return g_B;
        case 2: return g_X1;
        case 3: return g_X2;
        default: return ext;
    }
}
__device__ __forceinline__ float* dstbuf(int id, float* ext) {
    switch (id) {
        case 0: return g_A;
        case 1: return g_B;
        case 2: return g_X1;
        case 3: return g_X2;
        default: return ext;
    }
}

__device__ __forceinline__ uint32_t f2tf(float x) {
    uint32_t r; asm("cvt.rna.tf32.f32 %0, %1;" : "=r"(r) : "f"(x)); return r;
}

__device__ __forceinline__ void mma8(float c[4], uint32_t a0, uint32_t a1, uint32_t a2, uint32_t a3,
                                     uint32_t b0, uint32_t b1) {
    asm volatile("mma.sync.aligned.m16n8k8.row.col.f32.tf32.tf32.f32 "
                 "{%0,%1,%2,%3},{%4,%5,%6,%7},{%8,%9},{%0,%1,%2,%3};"
                 : "+f"(c[0]), "+f"(c[1]), "+f"(c[2]), "+f"(c[3])
                 : "r"(a0), "r"(a1), "r"(a2), "r"(a3), "r"(b0), "r"(b1));
}

// ---------------- index dtype detect ----------------
__global__ void detect_kernel(const int* __restrict__ he) {
    __shared__ int any;
    if (threadIdx.x == 0) any = 0;
    __syncthreads();
    if (he[2 * threadIdx.x + 1] != 0) atomicOr(&any, 1);
    __syncthreads();
    if (threadIdx.x == 0) g_idx64 = (any == 0) ? 1 : 0;
}

// ---------------- weight prep: transpose + tf32 hi/lo decompose into packed fragments ----
struct WList { const float* a[9]; const float* b[9]; int ncols[9]; };

__global__ void decompose_kernel(WList wl) {
    int w = blockIdx.y;
    int i = blockIdx.x * blockDim.x + threadIdx.x;   // 0..8191
    int t = i & 3, n = (i >> 2) & 127, kt = (i >> 9) & 7, c = i >> 12;
    int NC = wl.ncols[w];
    int k1 = c * 64 + kt * 8 + t, k2 = k1 + 4;
    float v1 = 0.f, v2 = 0.f;
    if (n < NC) {
        v1 = wl.a[w][k1 * NC + n];
        v2 = wl.a[w][k2 * NC + n];
        if (wl.b[w]) { v1 += wl.b[w][k1 * NC + n]; v2 += wl.b[w][k2 * NC + n]; }
    }
    float h1 = __uint_as_float(f2tf(v1));
    float h2 = __uint_as_float(f2tf(v2));
    g_Wp[w * 8192 + i] = make_float4(h1, h2, v1 - h1, v2 - h2);
}

__global__ void bias_combine_kernel(const float* __restrict__ a1, const float* __restrict__ b1,
                                    const float* __restrict__ a2, const float* __restrict__ b2) {
    int i = threadIdx.x;
    if (i < HID) { g_bsum1[i] = a1[i] + b1[i]; g_bsum2[i] = a2[i] + b2[i]; }
}

// ---------------- CSR build ----------------
__global__ void zero_deg_kernel() {
    int i = blockIdx.x * blockDim.x + threadIdx.x;
    if (i < NHE) g_deg_he[i] = 0;
    if (i < NN) { g_deg_nh[i] = 0; g_deg_nd[i] = 0; }
}

__global__ void count_kernel(const int* __restrict__ he, const int* __restrict__ ed) {
    int i = blockIdx.x * blockDim.x + threadIdx.x;
    if (i < NI) {
        atomicAdd(&g_deg_nh[clampi(idxat(he, i), NN)], 1);
        atomicAdd(&g_deg_he[clampi(idxat(he, NI + i), NHE)], 1);
    }
    if (i < NE) {
        atomicAdd(&g_deg_nd[clampi(idxat(ed, NE + i), NN)], 1);
    }
}

// fast two-level shuffle scan; 3 independent scans, blockIdx.x = which
__global__ void scan_kernel() {
    int which = blockIdx.x;
    const int* __restrict__ deg; int n; int* __restrict__ off; int* __restrict__ cur;
    float* __restrict__ inv;
    if (which == 0)      { deg = g_deg_he; n = NHE; off = g_off_he; cur = g_cur_he; inv = g_Binv; }
    else if (which == 1) { deg = g_deg_nh; n = NN;  off = g_off_nh; cur = g_cur_nh; inv = g_Dinv; }
    else                 { deg = g_deg_nd; n = NN;  off = g_off_nd; cur = g_cur_nd; inv = 0; }

    __shared__ int wsum[32];
    __shared__ int s_tot;
    __shared__ int s_run;
    int tid = threadIdx.x;
    int lane = tid & 31, wid = tid >> 5;
    if (tid == 0) s_run = 0;
    __syncthreads();

    int nt = (n + 4095) / 4096;
    for (int t = 0; t < nt; ++t) {
        int base = t * 4096 + tid * 4;
        int d0 = 0, d1 = 0, d2 = 0, d3 = 0;
        if (base + 3 < n) {
            int4 v = *(const int4*)&deg[base];
            d0 = v.x; d1 = v.y; d2 = v.z; d3 = v.w;
        } else {
            if (base + 0 < n) d0 = deg[base + 0];
            if (base + 1 < n) d1 = deg[base + 1];
            if (base + 2 < n) d2 = deg[base + 2];
            if (base + 3 < n) d3 = deg[base + 3];
        }
        int s = d0 + d1 + d2 + d3;
        int incl = s;
#pragma unroll
        for (int o = 1; o < 32; o <<= 1) {
            int v = __shfl_up_sync(0xFFFFFFFFu, incl, o);
            if (lane >= o) incl += v;
        }
        if (lane == 31) wsum[wid] = incl;
        __syncthreads();
        if (wid == 0) {
            int ws = wsum[lane];
            int wincl = ws;
#pragma unroll
            for (int o = 1; o < 32; o <<= 1) {
                int v = __shfl_up_sync(0xFFFFFFFFu, wincl, o);
                if (lane >= o) wincl += v;
            }
            wsum[lane] = wincl - ws;
            if (lane == 31) s_tot = wincl;
        }
        __syncthreads();
        int excl = s_run + wsum[wid] + (incl - s);
        int o0 = excl, o1 = o0 + d0, o2 = o1 + d1, o3 = o2 + d2;
        if (base + 3 < n) {
            *(int4*)&off[base] = make_int4(o0, o1, o2, o3);
            *(int4*)&cur[base] = make_int4(o0, o1, o2, o3);
            if (inv) {
                float4 f;
                f.x = d0 ? 1.0f / (float)d0 : 0.0f;
                f.y = d1 ? 1.0f / (float)d1 : 0.0f;
                f.z = d2 ? 1.0f / (float)d2 : 0.0f;
                f.w = d3 ? 1.0f / (float)d3 : 0.0f;
                *(float4*)&inv[base] = f;
            }
        } else {
            if (base + 0 < n) { off[base + 0] = o0; cur[base + 0] = o0; if (inv) inv[base + 0] = d0 ? 1.0f / (float)d0 : 0.0f; }
            if (base + 1 < n) { off[base + 1] = o1; cur[base + 1] = o1; if (inv) inv[base + 1] = d1 ? 1.0f / (float)d1 : 0.0f; }
            if (base + 2 < n) { off[base + 2] = o2; cur[base + 2] = o2; if (inv) inv[base + 2] = d2 ? 1.0f / (float)d2 : 0.0f; }
            if (base + 3 < n) { off[base + 3] = o3; cur[base + 3] = o3; if (inv) inv[base + 3] = d3 ? 1.0f / (float)d3 : 0.0f; }
        }
        __syncthreads();
        if (tid == 0) s_run += s_tot;
        __syncthreads();
    }
    if (tid == 0) off[n] = s_run;
}

__global__ void fill_kernel(const int* __restrict__ he, const int* __restrict__ ed) {
    int i = blockIdx.x * blockDim.x + threadIdx.x;
    if (i < NI) {
        int n = clampi(idxat(he, i), NN);
        int h = clampi(idxat(he, NI + i), NHE);
        g_list_he[atomicAdd(&g_cur_he[h], 1)] = n;
        g_list_nh[atomicAdd(&g_cur_nh[n], 1)] = h;
    }
    if (i < NE) {
        int s = clampi(idxat(ed, i), NN);
        int d = clampi(idxat(ed, NE + i), NN);
        g_list_nd[atomicAdd(&g_cur_nd[d], 1)] = s;
    }
}

// ---------------- gather segment-sums (1 warp per output row, 8-deep MLP) ----------------
#define GATHER_BODY(listarr, srcptr) \
    float ax = 0.f, ay = 0.f, az = 0.f, aw = 0.f; \
    int i = beg; \
    for (; i + 8 <= end; i += 8) { \
        int n0 = listarr[i], n1 = listarr[i + 1], n2 = listarr[i + 2], n3 = listarr[i + 3]; \
        int n4 = listarr[i + 4], n5 = listarr[i + 5], n6 = listarr[i + 6], n7 = listarr[i + 7]; \
        float4 v0 = srcptr[n0 * 32 + lane]; \
        float4 v1 = srcptr[n1 * 32 + lane]; \
        float4 v2 = srcptr[n2 * 32 + lane]; \
        float4 v3 = srcptr[n3 * 32 + lane]; \
        float4 v4 = srcptr[n4 * 32 + lane]; \
        float4 v5 = srcptr[n5 * 32 + lane]; \
        float4 v6 = srcptr[n6 * 32 + lane]; \
        float4 v7 = srcptr[n7 * 32 + lane]; \
        ax += ((v0.x + v1.x) + (v2.x + v3.x)) + ((v4.x + v5.x) + (v6.x + v7.x)); \
        ay += ((v0.y + v1.y) + (v2.y + v3.y)) + ((v4.y + v5.y) + (v6.y + v7.y)); \
        az += ((v0.z + v1.z) + (v2.z + v3.z)) + ((v4.z + v5.z) + (v6.z + v7.z)); \
        aw += ((v0.w + v1.w) + (v2.w + v3.w)) + ((v4.w + v5.w) + (v6.w + v7.w)); \
    } \
    for (; i < end; ++i) { \
        int nn_ = listarr[i]; \
        float4 v = srcptr[nn_ * 32 + lane]; \
        ax += v.x; ay += v.y; az += v.z; aw += v.w; \
    }

__global__ void gather_he_kernel() {
    int row = (blockIdx.x * blockDim.x + threadIdx.x) >> 5;
    if (row >= NHE) return;
    int lane = threadIdx.x & 31;
    int beg = g_off_he[row], end = g_off_he[row + 1];
    const float4* src = (const float4*)g_A;
    GATHER_BODY(g_list_he, src)
    float b = g_Binv[row];
    ((float4*)g_M)[row * 32 + lane] = make_float4(ax * b, ay * b, az * b, aw * b);
}

__global__ void gather_node_fuse_kernel(const float4* __restrict__ hcb,
                                        const float4* __restrict__ linb,
                                        int outsel) {
    int row = (blockIdx.x * blockDim.x + threadIdx.x) >> 5;
    if (row >= NN) return;
    int lane = threadIdx.x & 31;
    int beg = g_off_nh[row], end = g_off_nh[row + 1];
    const float4* m = (const float4*)g_M;
    GATHER_BODY(g_list_nh, m)
    float dinv = g_Dinv[row];
    float4 b1 = hcb[lane];
    float4 b2 = linb[lane];
    const float4* linP = (const float4*)g_B;
    float4 l = linP[row * 32 + lane];
    float4 r;
    r.x = leakyf(ax * dinv + b1.x + b2.x + l.x);
    r.y = leakyf(ay * dinv + b1.y + b2.y + l.y);
    r.z = leakyf(az * dinv + b1.z + b2.z + l.z);
    r.w = leakyf(aw * dinv + b1.w + b2.w + l.w);
    ((float4*)dstbuf(outsel, 0))[row * 32 + lane] = r;
}

__global__ void gather_edge_kernel(int srcsel) {
    int row = (blockIdx.x * blockDim.x + threadIdx.x) >> 5;
    if (row >= NN) return;
    int lane = threadIdx.x & 31;
    int beg = g_off_nd[row], end = g_off_nd[row + 1];
    const float4* src = (const float4*)srcbuf(srcsel, 0);
    GATHER_BODY(g_list_nd, src)
    ((float4*)g_A)[row * 32 + lane] = make_float4(ax, ay, az, aw);
}

// ---------------- 3xTF32 tensor-core GEMM with packed-B fragments ----------------
// C[M x KOUT] = A[M x 128] @ W[128 x KOUT]; W prepacked in g_Wp (widx).
// If gridDim.y == 2, blockIdx.y == 1 uses widxB/cselB (independent pair in one launch).
// MODE 0: C = acc ; MODE 1: C = acc + bias_ext ; MODE 2: C = leaky(acc + g_B + bsum)
template <int MODE, int NT>
__global__ __launch_bounds__(256, 2)
void gemm_tf32(const float* __restrict__ Aext, float* __restrict__ Cext,
               const float* __restrict__ bias_ext, int asel, int csel, int widx,
               int bs, int M, int widxB, int cselB) {
    constexpr int KOUT = NT * 8;
    if (blockIdx.y == 1) { widx = widxB; csel = cselB; }
    const float* A = srcbuf(asel, Aext);
    float* C = dstbuf(csel, Cext);

    extern __shared__ float sm[];
    float* As = sm;                           // [128][68]
    float4* Bs4 = (float4*)(sm + 128 * 68);   // [8 kt][128 n][4 t]

    int tid = threadIdx.x;
    int lane = tid & 31, warp = tid >> 5;
    int g = lane >> 2, t = lane & 3;
    int brow = blockIdx.x * 128;
    int wr = warp * 16;

    float c[NT][4];
#pragma unroll
    for (int nt = 0; nt < NT; ++nt)
#pragma unroll
        for (int j = 0; j < 4; ++j) c[nt][j] = 0.f;

#pragma unroll
    for (int chunk = 0; chunk < 2; ++chunk) {
        int k0 = chunk * 64;
        if (chunk) __syncthreads();
        // stage A chunk [128 rows][64 k]
#pragma unroll
        for (int p = 0; p < 8; ++p) {
            int idx = p * 256 + tid;
            int r = idx >> 4, c4 = (idx & 15) * 4;
            int gr = brow + r;
            float4 v = make_float4(0.f, 0.f, 0.f, 0.f);
            if (gr < M) v = *(const float4*)&A[(size_t)gr * 128 + k0 + c4];
            *(float4*)&As[r * 68 + c4] = v;
        }
        // stage packed B chunk: 4096 float4 straight copy
        const float4* Wp = g_Wp + widx * 8192 + chunk * 4096;
#pragma unroll
        for (int p = 0; p < 16; ++p) {
            int idx = p * 256 + tid;
            Bs4[idx] = Wp[idx];
        }
        __syncthreads();

#pragma unroll
        for (int kt = 0; kt < 8; ++kt) {
            int kk = kt * 8;
            float a0 = As[(wr + g) * 68 + kk + t];
            float a1 = As[(wr + g + 8) * 68 + kk + t];
            float a2 = As[(wr + g) * 68 + kk + t + 4];
            float a3 = As[(wr + g + 8) * 68 + kk + t + 4];
            uint32_t ah0 = f2tf(a0), ah1 = f2tf(a1), ah2 = f2tf(a2), ah3 = f2tf(a3);
            uint32_t al0 = __float_as_uint(a0 - __uint_as_float(ah0));
            uint32_t al1 = __float_as_uint(a1 - __uint_as_float(ah1));
            uint32_t al2 = __float_as_uint(a2 - __uint_as_float(ah2));
            uint32_t al3 = __float_as_uint(a3 - __uint_as_float(ah3));
#pragma unroll
            for (int nt = 0; nt < NT; ++nt) {
                float4 b = Bs4[kt * 512 + (nt * 8 + g) * 4 + t];
                uint32_t b0h = __float_as_uint(b.x);
                uint32_t b1h = __float_as_uint(b.y);
                uint32_t b0l = __float_as_uint(b.z);
                uint32_t b1l = __float_as_uint(b.w);
                mma8(c[nt], ah0, ah1, ah2, ah3, b0h, b1h);
                mma8(c[nt], al0, al1, al2, al3, b0h, b1h);
                mma8(c[nt], ah0, ah1, ah2, ah3, b0l, b1l);
            }
        }
    }

    // epilogue
    const float* bsum = bs ? g_bsum2 : g_bsum1;
    int r0 = brow + wr + g;
    int r1 = r0 + 8;
#pragma unroll
    for (int nt = 0; nt < NT; ++nt) {
        int col = nt * 8 + 2 * t;
        if (r0 < M) {
            float v0 = c[nt][0], v1 = c[nt][1];
            if (MODE == 1) { v0 += bias_ext[col]; v1 += bias_ext[col + 1]; }
            if (MODE == 2) {
                v0 = leakyf(v0 + g_B[(size_t)r0 * 128 + col] + bsum[col]);
                v1 = leakyf(v1 + g_B[(size_t)r0 * 128 + col + 1] + bsum[col + 1]);
            }
            *(float2*)&C[(size_t)r0 * KOUT + col] = make_float2(v0, v1);
        }
        if (r1 < M) {
            float v2 = c[nt][2], v3 = c[nt][3];
            if (MODE == 1) { v2 += bias_ext[col]; v3 += bias_ext[col + 1]; }
            if (MODE == 2) {
                v2 = leakyf(v2 + g_B[(size_t)r1 * 128 + col] + bsum[col]);
                v3 = leakyf(v3 + g_B[(size_t)r1 * 128 + col + 1] + bsum[col + 1]);
            }
            *(float2*)&C[(size_t)r1 * KOUT + col] = make_float2(v2, v3);
        }
    }
}

// ---------------- launch ----------------
extern "C" void kernel_launch(void* const* d_in, const int* in_sizes, int n_in,
                              void* d_out, int out_size) {
    const float* X     = (const float*)d_in[0];
    const int* eidx    = (const int*)d_in[1];
    const int* hidx    = (const int*)d_in[2];
    const float* hc1w  = (const float*)d_in[3];
    const float* hc1b  = (const float*)d_in[4];
    const float* lin1w = (const float*)d_in[5];
    const float* lin1b = (const float*)d_in[6];
    const float* hc2w  = (const float*)d_in[7];
    const float* hc2b  = (const float*)d_in[8];
    const float* lin2w = (const float*)d_in[9];
    const float* lin2b = (const float*)d_in[10];
    const float* c1wrel  = (const float*)d_in[11];
    const float* c1brel  = (const float*)d_in[12];
    const float* c1wroot = (const float*)d_in[13];
    const float* glin1w  = (const float*)d_in[14];
    const float* glin1b  = (const float*)d_in[15];
    const float* c2wrel  = (const float*)d_in[16];
    const float* c2brel  = (const float*)d_in[17];
    const float* c2wroot = (const float*)d_in[18];
    const float* glin2w  = (const float*)d_in[19];
    const float* glin2b  = (const float*)d_in[20];
    const float* fcw = (const float*)d_in[21];
    const float* fcb = (const float*)d_in[22];

    const size_t NX = (size_t)NN * HID;
    const size_t NYsz = (size_t)NN * OUTC;
    bool full_out = ((size_t)out_size >= NX + NYsz);
    float* outX = (float*)d_out;
    float* outY = full_out ? (outX + NX) : (float*)d_out;
    int final_csel = full_out ? -1 : 3;
    int fc_asel    = full_out ? -1 : 3;
    const float* fc_Aext = full_out ? outX : (const float*)0;

    const int TPB = 256;
    const int SMEMSZ = 128 * 68 * 4 + 4096 * 16;    // 100352 B
    int gG = (NN + 127) / 128;
    int gbE   = (NE + TPB - 1) / TPB;
    int gbHEw = (NHE * 32 + TPB - 1) / TPB;
    int gbNw  = (NN * 32 + TPB - 1) / TPB;

    cudaFuncSetAttribute((const void*)gemm_tf32<0, 16>, cudaFuncAttributeMaxDynamicSharedMemorySize, SMEMSZ);
    cudaFuncSetAttribute((const void*)gemm_tf32<2, 16>, cudaFuncAttributeMaxDynamicSharedMemorySize, SMEMSZ);
    cudaFuncSetAttribute((const void*)gemm_tf32<1, 8>,  cudaFuncAttributeMaxDynamicSharedMemorySize, SMEMSZ);

    // ---- weight prep ----
    WList wl;
    wl.a[0] = hc1w;    wl.b[0] = 0;      wl.ncols[0] = 128;
    wl.a[1] = lin1w;   wl.b[1] = 0;      wl.ncols[1] = 128;
    wl.a[2] = hc2w;    wl.b[2] = 0;      wl.ncols[2] = 128;
    wl.a[3] = lin2w;   wl.b[3] = 0;      wl.ncols[3] = 128;
    wl.a[4] = c1wrel;  wl.b[4] = 0;      wl.ncols[4] = 128;
    wl.a[5] = c1wroot; wl.b[5] = glin1w; wl.ncols[5] = 128;
    wl.a[6] = c2wrel;  wl.b[6] = 0;      wl.ncols[6] = 128;
    wl.a[7] = c2wroot; wl.b[7] = glin2w; wl.ncols[7] = 128;
    wl.a[8] = fcw;     wl.b[8] = 0;      wl.ncols[8] = 64;
    decompose_kernel<<<dim3(32, 9), TPB>>>(wl);
    bias_combine_kernel<<<1, 128>>>(c1brel, glin1b, c2brel, glin2b);

    // ---- dtype detect + CSR build ----
    detect_kernel<<<1, 256>>>(hidx);
    zero_deg_kernel<<<(NN + TPB - 1) / TPB, TPB>>>();
    count_kernel<<<gbE, TPB>>>(hidx, eidx);
    scan_kernel<<<3, 1024>>>();
    fill_kernel<<<gbE, TPB>>>(hidx, eidx);

    // ---- layer 1 (hypergraph): paired GEMMs in one launch ----
    gemm_tf32<0, 16><<<dim3(gG, 2), TPB, SMEMSZ>>>(X, 0, 0, -1, 0, 0, 0, NN, 1, 1);  // g_A=X@hc1w ; g_B=X@lin1w
    gather_he_kernel<<<gbHEw, TPB>>>();
    gather_node_fuse_kernel<<<gbNw, TPB>>>((const float4*)hc1b, (const float4*)lin1b, 2);

    // ---- layer 2 (hypergraph) ----
    gemm_tf32<0, 16><<<dim3(gG, 2), TPB, SMEMSZ>>>(0, 0, 0, 2, 0, 2, 0, NN, 3, 1);   // g_A=g_X1@hc2w ; g_B=g_X1@lin2w
    gather_he_kernel<<<gbHEw, TPB>>>();
    gather_node_fuse_kernel<<<gbNw, TPB>>>((const float4*)hc2b, (const float4*)lin2b, 3);

    // ---- layer 3 (graph) ----
    gather_edge_kernel<<<gbNw, TPB>>>(3);                                            // g_A = segsum(g_X2)
    gemm_tf32<0, 16><<<gG, TPB, SMEMSZ>>>(0, 0, 0, 0, 1, 4, 0, NN, 4, 1);            // g_B = g_A @ c1wrel
    gemm_tf32<2, 16><<<gG, TPB, SMEMSZ>>>(0, 0, 0, 3, 2, 5, 0, NN, 5, 2);            // g_X1 = leaky(g_X2@Wc1 + g_B + bsum1)

    // ---- layer 4 (graph) ----
    gather_edge_kernel<<<gbNw, TPB>>>(2);                                            // g_A = segsum(g_X1)
    gemm_tf32<0, 16><<<gG, TPB, SMEMSZ>>>(0, 0, 0, 0, 1, 6, 0, NN, 6, 1);            // g_B = g_A @ c2wrel
    gemm_tf32<2, 16><<<gG, TPB, SMEMSZ>>>(0, outX, 0, 2, final_csel, 7, 1, NN, 7, final_csel);  // X4

    // ---- fc head ----
    gemm_tf32<1, 8><<<gG, TPB, SMEMSZ>>>(fc_Aext, outY, fcb, fc_asel, -1, 8, 0, NN, 8, -1);
}

// round 14
// speedup vs baseline: 1.4253x; 1.0337x over previous
#include <cuda_runtime.h>
#include <cstdint>

#define NN   50000
#define NHE  10000
#define NE   800000
#define NI   800000
#define HID  128
#define OUTC 64

// ---------------- device scratch ----------------
__device__ __align__(16) float g_A[NN * HID];
__device__ __align__(16) float g_B[NN * HID];
__device__ __align__(16) float g_X1[NN * HID];
__device__ __align__(16) float g_X2[NN * HID];
__device__ __align__(16) float g_M[NHE * HID];
// packed tf32 weights: per w, [chunk(2)][kt(8)][n(128)][t(4)] float4 = (b0h,b1h,b0l,b1l)
__device__ __align__(16) float4 g_Wp[9 * 8192];
__device__ __align__(16) float g_bsum1[HID];
__device__ __align__(16) float g_bsum2[HID];
__device__ __align__(16) float g_Binv[NHE];
__device__ __align__(16) float g_Dinv[NN];

__device__ int g_idx64;
__device__ __align__(16) int g_deg_he[NHE];
__device__ __align__(16) int g_off_he[NHE + 1];
__device__ __align__(16) int g_cur_he[NHE];
__device__ __align__(16) int g_deg_nh[NN];
__device__ __align__(16) int g_off_nh[NN + 1];
__device__ __align__(16) int g_cur_nh[NN];
__device__ __align__(16) int g_deg_nd[NN];
__device__ __align__(16) int g_off_nd[NN + 1];
__device__ __align__(16) int g_cur_nd[NN];
__device__ int g_list_he[NI];
__device__ int g_list_nh[NI];
__device__ int g_list_nd[NE];

__device__ __forceinline__ float leakyf(float x) { return x >= 0.f ? x : 0.01f * x; }
__device__ __forceinline__ int clampi(int v, int hi) { return v < 0 ? 0 : (v >= hi ? hi - 1 : v); }

__device__ __forceinline__ int idxat(const int* __restrict__ a, int pos) {
    return g_idx64 ? a[2 * (long long)pos] : a[pos];
}

__device__ __forceinline__ const float* srcbuf(int id, const float* ext) {
    switch (id) {
        case 0: return g_A;
        case 1: return g_B;
        case 2: return g_X1;
        case 3: return g_X2;
        default: return ext;
    }
}
__device__ __forceinline__ float* dstbuf(int id, float* ext) {
    switch (id) {
        case 0: return g_A;
        case 1: return g_B;
        case 2: return g_X1;
        case 3: return g_X2;
        default: return ext;
    }
}

__device__ __forceinline__ uint32_t f2tf(float x) {
    uint32_t r; asm("cvt.rna.tf32.f32 %0, %1;" : "=r"(r) : "f"(x)); return r;
}

__device__ __forceinline__ void mma8(float c[4], uint32_t a0, uint32_t a1, uint32_t a2, uint32_t a3,
                                     uint32_t b0, uint32_t b1) {
    asm volatile("mma.sync.aligned.m16n8k8.row.col.f32.tf32.tf32.f32 "
                 "{%0,%1,%2,%3},{%4,%5,%6,%7},{%8,%9},{%0,%1,%2,%3};"
                 : "+f"(c[0]), "+f"(c[1]), "+f"(c[2]), "+f"(c[3])
                 : "r"(a0), "r"(a1), "r"(a2), "r"(a3), "r"(b0), "r"(b1));
}

// ---------------- weight prep: transpose + tf32 hi/lo decompose into packed fragments ----
// grid y: 0..8 = weights ; 9 = bias combine row
struct WList {
    const float* a[9]; const float* b[9]; int ncols[9];
    const float* ba1; const float* bb1; const float* ba2; const float* bb2;
};

__global__ void decompose_kernel(WList wl) {
    int w = blockIdx.y;
    int i = blockIdx.x * blockDim.x + threadIdx.x;   // 0..8191
    if (w == 9) {
        if (blockIdx.x == 0 && i < HID) {
            g_bsum1[i] = wl.ba1[i] + wl.bb1[i];
            g_bsum2[i] = wl.ba2[i] + wl.bb2[i];
        }
        return;
    }
    int t = i & 3, n = (i >> 2) & 127, kt = (i >> 9) & 7, c = i >> 12;
    int NC = wl.ncols[w];
    int k1 = c * 64 + kt * 8 + t, k2 = k1 + 4;
    float v1 = 0.f, v2 = 0.f;
    if (n < NC) {
        v1 = wl.a[w][k1 * NC + n];
        v2 = wl.a[w][k2 * NC + n];
        if (wl.b[w]) { v1 += wl.b[w][k1 * NC + n]; v2 += wl.b[w][k2 * NC + n]; }
    }
    float h1 = __uint_as_float(f2tf(v1));
    float h2 = __uint_as_float(f2tf(v2));
    g_Wp[w * 8192 + i] = make_float4(h1, h2, v1 - h1, v2 - h2);
}

// ---------------- CSR build (zero + dtype detect fused) ----------------
__global__ void zero_deg_kernel(const int* __restrict__ he) {
    int i = blockIdx.x * blockDim.x + threadIdx.x;
    if (blockIdx.x == 0) {
        __shared__ int any;
        if (threadIdx.x == 0) any = 0;
        __syncthreads();
        if (he[2 * threadIdx.x + 1] != 0) atomicOr(&any, 1);
        __syncthreads();
        if (threadIdx.x == 0) g_idx64 = (any == 0) ? 1 : 0;
    }
    if (i < NHE) g_deg_he[i] = 0;
    if (i < NN) { g_deg_nh[i] = 0; g_deg_nd[i] = 0; }
}

__global__ void count_kernel(const int* __restrict__ he, const int* __restrict__ ed) {
    int i = blockIdx.x * blockDim.x + threadIdx.x;
    if (i < NI) {
        atomicAdd(&g_deg_nh[clampi(idxat(he, i), NN)], 1);
        atomicAdd(&g_deg_he[clampi(idxat(he, NI + i), NHE)], 1);
    }
    if (i < NE) {
        atomicAdd(&g_deg_nd[clampi(idxat(ed, NE + i), NN)], 1);
    }
}

// fast two-level shuffle scan; 3 independent scans, blockIdx.x = which
__global__ void scan_kernel() {
    int which = blockIdx.x;
    const int* __restrict__ deg; int n; int* __restrict__ off; int* __restrict__ cur;
    float* __restrict__ inv;
    if (which == 0)      { deg = g_deg_he; n = NHE; off = g_off_he; cur = g_cur_he; inv = g_Binv; }
    else if (which == 1) { deg = g_deg_nh; n = NN;  off = g_off_nh; cur = g_cur_nh; inv = g_Dinv; }
    else                 { deg = g_deg_nd; n = NN;  off = g_off_nd; cur = g_cur_nd; inv = 0; }

    __shared__ int wsum[32];
    __shared__ int s_tot;
    __shared__ int s_run;
    int tid = threadIdx.x;
    int lane = tid & 31, wid = tid >> 5;
    if (tid == 0) s_run = 0;
    __syncthreads();

    int nt = (n + 4095) / 4096;
    for (int t = 0; t < nt; ++t) {
        int base = t * 4096 + tid * 4;
        int d0 = 0, d1 = 0, d2 = 0, d3 = 0;
        if (base + 3 < n) {
            int4 v = *(const int4*)&deg[base];
            d0 = v.x; d1 = v.y; d2 = v.z; d3 = v.w;
        } else {
            if (base + 0 < n) d0 = deg[base + 0];
            if (base + 1 < n) d1 = deg[base + 1];
            if (base + 2 < n) d2 = deg[base + 2];
            if (base + 3 < n) d3 = deg[base + 3];
        }
        int s = d0 + d1 + d2 + d3;
        int incl = s;
#pragma unroll
        for (int o = 1; o < 32; o <<= 1) {
            int v = __shfl_up_sync(0xFFFFFFFFu, incl, o);
            if (lane >= o) incl += v;
        }
        if (lane == 31) wsum[wid] = incl;
        __syncthreads();
        if (wid == 0) {
            int ws = wsum[lane];
            int wincl = ws;
#pragma unroll
            for (int o = 1; o < 32; o <<= 1) {
                int v = __shfl_up_sync(0xFFFFFFFFu, wincl, o);
                if (lane >= o) wincl += v;
            }
            wsum[lane] = wincl - ws;
            if (lane == 31) s_tot = wincl;
        }
        __syncthreads();
        int excl = s_run + wsum[wid] + (incl - s);
        int o0 = excl, o1 = o0 + d0, o2 = o1 + d1, o3 = o2 + d2;
        if (base + 3 < n) {
            *(int4*)&off[base] = make_int4(o0, o1, o2, o3);
            *(int4*)&cur[base] = make_int4(o0, o1, o2, o3);
            if (inv) {
                float4 f;
                f.x = d0 ? 1.0f / (float)d0 : 0.0f;
                f.y = d1 ? 1.0f / (float)d1 : 0.0f;
                f.z = d2 ? 1.0f / (float)d2 : 0.0f;
                f.w = d3 ? 1.0f / (float)d3 : 0.0f;
                *(float4*)&inv[base] = f;
            }
        } else {
            if (base + 0 < n) { off[base + 0] = o0; cur[base + 0] = o0; if (inv) inv[base + 0] = d0 ? 1.0f / (float)d0 : 0.0f; }
            if (base + 1 < n) { off[base + 1] = o1; cur[base + 1] = o1; if (inv) inv[base + 1] = d1 ? 1.0f / (float)d1 : 0.0f; }
            if (base + 2 < n) { off[base + 2] = o2; cur[base + 2] = o2; if (inv) inv[base + 2] = d2 ? 1.0f / (float)d2 : 0.0f; }
            if (base + 3 < n) { off[base + 3] = o3; cur[base + 3] = o3; if (inv) inv[base + 3] = d3 ? 1.0f / (float)d3 : 0.0f; }
        }
        __syncthreads();
        if (tid == 0) s_run += s_tot;
        __syncthreads();
    }
    if (tid == 0) off[n] = s_run;
}

__global__ void fill_kernel(const int* __restrict__ he, const int* __restrict__ ed) {
    int i = blockIdx.x * blockDim.x + threadIdx.x;
    if (i < NI) {
        int n = clampi(idxat(he, i), NN);
        int h = clampi(idxat(he, NI + i), NHE);
        g_list_he[atomicAdd(&g_cur_he[h], 1)] = n;
        g_list_nh[atomicAdd(&g_cur_nh[n], 1)] = h;
    }
    if (i < NE) {
        int s = clampi(idxat(ed, i), NN);
        int d = clampi(idxat(ed, NE + i), NN);
        g_list_nd[atomicAdd(&g_cur_nd[d], 1)] = s;
    }
}

// ---------------- gather segment-sums (1 warp per output row, 8-deep MLP) ----------------
#define GATHER_BODY(listarr, srcptr) \
    float ax = 0.f, ay = 0.f, az = 0.f, aw = 0.f; \
    int i = beg; \
    for (; i + 8 <= end; i += 8) { \
        int n0 = listarr[i], n1 = listarr[i + 1], n2 = listarr[i + 2], n3 = listarr[i + 3]; \
        int n4 = listarr[i + 4], n5 = listarr[i + 5], n6 = listarr[i + 6], n7 = listarr[i + 7]; \
        float4 v0 = srcptr[n0 * 32 + lane]; \
        float4 v1 = srcptr[n1 * 32 + lane]; \
        float4 v2 = srcptr[n2 * 32 + lane]; \
        float4 v3 = srcptr[n3 * 32 + lane]; \
        float4 v4 = srcptr[n4 * 32 + lane]; \
        float4 v5 = srcptr[n5 * 32 + lane]; \
        float4 v6 = srcptr[n6 * 32 + lane]; \
        float4 v7 = srcptr[n7 * 32 + lane]; \
        ax += ((v0.x + v1.x) + (v2.x + v3.x)) + ((v4.x + v5.x) + (v6.x + v7.x)); \
        ay += ((v0.y + v1.y) + (v2.y + v3.y)) + ((v4.y + v5.y) + (v6.y + v7.y)); \
        az += ((v0.z + v1.z) + (v2.z + v3.z)) + ((v4.z + v5.z) + (v6.z + v7.z)); \
        aw += ((v0.w + v1.w) + (v2.w + v3.w)) + ((v4.w + v5.w) + (v6.w + v7.w)); \
    } \
    for (; i < end; ++i) { \
        int nn_ = listarr[i]; \
        float4 v = srcptr[nn_ * 32 + lane]; \
        ax += v.x; ay += v.y; az += v.z; aw += v.w; \
    }

__global__ void gather_he_kernel() {
    int row = (blockIdx.x * blockDim.x + threadIdx.x) >> 5;
    if (row >= NHE) return;
    int lane = threadIdx.x & 31;
    int beg = g_off_he[row], end = g_off_he[row + 1];
    const float4* src = (const float4*)g_A;
    GATHER_BODY(g_list_he, src)
    float b = g_Binv[row];
    ((float4*)g_M)[row * 32 + lane] = make_float4(ax * b, ay * b, az * b, aw * b);
}

__global__ void gather_node_fuse_kernel(const float4* __restrict__ hcb,
                                        const float4* __restrict__ linb,
                                        int outsel) {
    int row = (blockIdx.x * blockDim.x + threadIdx.x) >> 5;
    if (row >= NN) return;
    int lane = threadIdx.x & 31;
    int beg = g_off_nh[row], end = g_off_nh[row + 1];
    const float4* m = (const float4*)g_M;
    GATHER_BODY(g_list_nh, m)
    float dinv = g_Dinv[row];
    float4 b1 = hcb[lane];
    float4 b2 = linb[lane];
    const float4* linP = (const float4*)g_B;
    float4 l = linP[row * 32 + lane];
    float4 r;
    r.x = leakyf(ax * dinv + b1.x + b2.x + l.x);
    r.y = leakyf(ay * dinv + b1.y + b2.y + l.y);
    r.z = leakyf(az * dinv + b1.z + b2.z + l.z);
    r.w = leakyf(aw * dinv + b1.w + b2.w + l.w);
    ((float4*)dstbuf(outsel, 0))[row * 32 + lane] = r;
}

__global__ void gather_edge_kernel(int srcsel) {
    int row = (blockIdx.x * blockDim.x + threadIdx.x) >> 5;
    if (row >= NN) return;
    int lane = threadIdx.x & 31;
    int beg = g_off_nd[row], end = g_off_nd[row + 1];
    const float4* src = (const float4*)srcbuf(srcsel, 0);
    GATHER_BODY(g_list_nd, src)
    ((float4*)g_A)[row * 32 + lane] = make_float4(ax, ay, az, aw);
}

// ---------------- 3xTF32 tensor-core GEMM with packed-B fragments ----------------
// NCH=2: C[M x KOUT] = A[M x 128] @ W(widx).
// NCH=4: C = A[M x 128] @ W(widx) + A2(asel2)[M x 128] @ W(widx2)  (K-concat fusion).
// If gridDim.y == 2, blockIdx.y == 1 uses widxB/cselB (independent pair in one launch).
// MODE 0: C = acc ; MODE 1: C = acc + bias_ext ; MODE 5: C = leaky(acc + bsum(bs))
template <int MODE, int NT, int NCH>
__global__ __launch_bounds__(256, 2)
void gemm_tf32(const float* __restrict__ Aext, float* __restrict__ Cext,
               const float* __restrict__ bias_ext, int asel, int asel2, int csel,
               int widx, int widx2, int bs, int M, int widxB, int cselB) {
    constexpr int KOUT = NT * 8;
    if (blockIdx.y == 1) { widx = widxB; csel = cselB; }
    const float* A = srcbuf(asel, Aext);
    const float* A2 = (NCH == 4) ? srcbuf(asel2, 0) : A;
    float* C = dstbuf(csel, Cext);

    extern __shared__ float sm[];
    float* As = sm;                           // [128][68]
    float4* Bs4 = (float4*)(sm + 128 * 68);   // [8 kt][128 n][4 t]

    int tid = threadIdx.x;
    int lane = tid & 31, warp = tid >> 5;
    int g = lane >> 2, t = lane & 3;
    int brow = blockIdx.x * 128;
    int wr = warp * 16;

    float c[NT][4];
#pragma unroll
    for (int nt = 0; nt < NT; ++nt)
#pragma unroll
        for (int j = 0; j < 4; ++j) c[nt][j] = 0.f;

#pragma unroll
    for (int chunk = 0; chunk < NCH; ++chunk) {
        const float* Asrc = (NCH == 4 && chunk >= 2) ? A2 : A;
        int k0 = (chunk & 1) * 64;
        int w = (NCH == 4 && chunk >= 2) ? widx2 : widx;
        if (chunk) __syncthreads();
        // stage A chunk [128 rows][64 k]
#pragma unroll
        for (int p = 0; p < 8; ++p) {
            int idx = p * 256 + tid;
            int r = idx >> 4, c4 = (idx & 15) * 4;
            int gr = brow + r;
            float4 v = make_float4(0.f, 0.f, 0.f, 0.f);
            if (gr < M) v = *(const float4*)&Asrc[(size_t)gr * 128 + k0 + c4];
            *(float4*)&As[r * 68 + c4] = v;
        }
        // stage packed B chunk: 4096 float4 straight copy
        const float4* Wp = g_Wp + w * 8192 + (chunk & 1) * 4096;
#pragma unroll
        for (int p = 0; p < 16; ++p) {
            int idx = p * 256 + tid;
            Bs4[idx] = Wp[idx];
        }
        __syncthreads();

#pragma unroll
        for (int kt = 0; kt < 8; ++kt) {
            int kk = kt * 8;
            float a0 = As[(wr + g) * 68 + kk + t];
            float a1 = As[(wr + g + 8) * 68 + kk + t];
            float a2 = As[(wr + g) * 68 + kk + t + 4];
            float a3 = As[(wr + g + 8) * 68 + kk + t + 4];
            uint32_t ah0 = f2tf(a0), ah1 = f2tf(a1), ah2 = f2tf(a2), ah3 = f2tf(a3);
            uint32_t al0 = __float_as_uint(a0 - __uint_as_float(ah0));
            uint32_t al1 = __float_as_uint(a1 - __uint_as_float(ah1));
            uint32_t al2 = __float_as_uint(a2 - __uint_as_float(ah2));
            uint32_t al3 = __float_as_uint(a3 - __uint_as_float(ah3));
#pragma unroll
            for (int nt = 0; nt < NT; ++nt) {
                float4 b = Bs4[kt * 512 + (nt * 8 + g) * 4 + t];
                uint32_t b0h = __float_as_uint(b.x);
                uint32_t b1h = __float_as_uint(b.y);
                uint32_t b0l = __float_as_uint(b.z);
                uint32_t b1l = __float_as_uint(b.w);
                mma8(c[nt], ah0, ah1, ah2, ah3, b0h, b1h);
                mma8(c[nt], al0, al1, al2, al3, b0h, b1h);
                mma8(c[nt], ah0, ah1, ah2, ah3, b0l, b1l);
            }
        }
    }

    // epilogue
    const float* bsum = bs ? g_bsum2 : g_bsum1;
    int r0 = brow + wr + g;
    int r1 = r0 + 8;
#pragma unroll
    for (int nt = 0; nt < NT; ++nt) {
        int col = nt * 8 + 2 * t;
        if (r0 < M) {
            float v0 = c[nt][0], v1 = c[nt][1];
            if (MODE == 1) { v0 += bias_ext[col]; v1 += bias_ext[col + 1]; }
            if (MODE == 5) {
                v0 = leakyf(v0 + bsum[col]);
                v1 = leakyf(v1 + bsum[col + 1]);
            }
            *(float2*)&C[(size_t)r0 * KOUT + col] = make_float2(v0, v1);
        }
        if (r1 < M) {
            float v2 = c[nt][2], v3 = c[nt][3];
            if (MODE == 1) { v2 += bias_ext[col]; v3 += bias_ext[col + 1]; }
            if (MODE == 5) {
                v2 = leakyf(v2 + bsum[col]);
                v3 = leakyf(v3 + bsum[col + 1]);
            }
            *(float2*)&C[(size_t)r1 * KOUT + col] = make_float2(v2, v3);
        }
    }
}

// ---------------- launch ----------------
extern "C" void kernel_launch(void* const* d_in, const int* in_sizes, int n_in,
                              void* d_out, int out_size) {
    const float* X     = (const float*)d_in[0];
    const int* eidx    = (const int*)d_in[1];
    const int* hidx    = (const int*)d_in[2];
    const float* hc1w  = (const float*)d_in[3];
    const float* hc1b  = (const float*)d_in[4];
    const float* lin1w = (const float*)d_in[5];
    const float* lin1b = (const float*)d_in[6];
    const float* hc2w  = (const float*)d_in[7];
    const float* hc2b  = (const float*)d_in[8];
    const float* lin2w = (const float*)d_in[9];
    const float* lin2b = (const float*)d_in[10];
    const float* c1wrel  = (const float*)d_in[11];
    const float* c1brel  = (const float*)d_in[12];
    const float* c1wroot = (const float*)d_in[13];
    const float* glin1w  = (const float*)d_in[14];
    const float* glin1b  = (const float*)d_in[15];
    const float* c2wrel  = (const float*)d_in[16];
    const float* c2brel  = (const float*)d_in[17];
    const float* c2wroot = (const float*)d_in[18];
    const float* glin2w  = (const float*)d_in[19];
    const float* glin2b  = (const float*)d_in[20];
    const float* fcw = (const float*)d_in[21];
    const float* fcb = (const float*)d_in[22];

    const size_t NX = (size_t)NN * HID;
    const size_t NYsz = (size_t)NN * OUTC;
    bool full_out = ((size_t)out_size >= NX + NYsz);
    float* outX = (float*)d_out;
    float* outY = full_out ? (outX + NX) : (float*)d_out;
    int final_csel = full_out ? -1 : 3;
    int fc_asel    = full_out ? -1 : 3;
    const float* fc_Aext = full_out ? outX : (const float*)0;

    const int TPB = 256;
    const int SMEMSZ = 128 * 68 * 4 + 4096 * 16;    // 100352 B
    int gG = (NN + 127) / 128;
    int gbE   = (NE + TPB - 1) / TPB;
    int gbHEw = (NHE * 32 + TPB - 1) / TPB;
    int gbNw  = (NN * 32 + TPB - 1) / TPB;

    cudaFuncSetAttribute((const void*)gemm_tf32<0, 16, 2>, cudaFuncAttributeMaxDynamicSharedMemorySize, SMEMSZ);
    cudaFuncSetAttribute((const void*)gemm_tf32<5, 16, 4>, cudaFuncAttributeMaxDynamicSharedMemorySize, SMEMSZ);
    cudaFuncSetAttribute((const void*)gemm_tf32<1, 8, 2>,  cudaFuncAttributeMaxDynamicSharedMemorySize, SMEMSZ);

    // ---- weight prep (bias combine fused as grid row 9) ----
    WList wl;
    wl.a[0] = hc1w;    wl.b[0] = 0;      wl.ncols[0] = 128;
    wl.a[1] = lin1w;   wl.b[1] = 0;      wl.ncols[1] = 128;
    wl.a[2] = hc2w;    wl.b[2] = 0;      wl.ncols[2] = 128;
    wl.a[3] = lin2w;   wl.b[3] = 0;      wl.ncols[3] = 128;
    wl.a[4] = c1wrel;  wl.b[4] = 0;      wl.ncols[4] = 128;
    wl.a[5] = c1wroot; wl.b[5] = glin1w; wl.ncols[5] = 128;
    wl.a[6] = c2wrel;  wl.b[6] = 0;      wl.ncols[6] = 128;
    wl.a[7] = c2wroot; wl.b[7] = glin2w; wl.ncols[7] = 128;
    wl.a[8] = fcw;     wl.b[8] = 0;      wl.ncols[8] = 64;
    wl.ba1 = c1brel; wl.bb1 = glin1b; wl.ba2 = c2brel; wl.bb2 = glin2b;
    decompose_kernel<<<dim3(32, 10), TPB>>>(wl);

    // ---- CSR build (detect fused into zero) ----
    zero_deg_kernel<<<(NN + TPB - 1) / TPB, TPB>>>(hidx);
    count_kernel<<<gbE, TPB>>>(hidx, eidx);
    scan_kernel<<<3, 1024>>>();
    fill_kernel<<<gbE, TPB>>>(hidx, eidx);

    // ---- layer 1 (hypergraph): paired GEMMs in one launch ----
    gemm_tf32<0, 16, 2><<<dim3(gG, 2), TPB, SMEMSZ>>>(X, 0, 0, -1, -1, 0, 0, 0, 0, NN, 1, 1);  // g_A=X@hc1w ; g_B=X@lin1w
    gather_he_kernel<<<gbHEw, TPB>>>();
    gather_node_fuse_kernel<<<gbNw, TPB>>>((const float4*)hc1b, (const float4*)lin1b, 2);

    // ---- layer 2 (hypergraph) ----
    gemm_tf32<0, 16, 2><<<dim3(gG, 2), TPB, SMEMSZ>>>(0, 0, 0, 2, -1, 0, 2, 0, 0, NN, 3, 1);   // g_A=g_X1@hc2w ; g_B=g_X1@lin2w
    gather_he_kernel<<<gbHEw, TPB>>>();
    gather_node_fuse_kernel<<<gbNw, TPB>>>((const float4*)hc2b, (const float4*)lin2b, 3);

    // ---- layer 3 (graph): K-concat fused GEMM ----
    gather_edge_kernel<<<gbNw, TPB>>>(3);                                            // g_A = segsum(g_X2)
    gemm_tf32<5, 16, 4><<<gG, TPB, SMEMSZ>>>(0, 0, 0, 0, 3, 2, 4, 5, 0, NN, 4, 2);   // g_X1 = leaky(g_A@c1wrel + g_X2@Wc1 + bsum1)

    // ---- layer 4 (graph) ----
    gather_edge_kernel<<<gbNw, TPB>>>(2);                                            // g_A = segsum(g_X1)
    gemm_tf32<5, 16, 4><<<gG, TPB, SMEMSZ>>>(0, outX, 0, 0, 2, final_csel, 6, 7, 1, NN, 6, final_csel);  // X4

    // ---- fc head ----
    gemm_tf32<1, 8, 2><<<gG, TPB, SMEMSZ>>>(fc_Aext, outY, fcb, fc_asel, -1, -1, 8, 8, 0, NN, 8, -1);
}

// round 16
// speedup vs baseline: 1.7870x; 1.2538x over previous
#include <cuda_runtime.h>
#include <cstdint>

#define NN   50000
#define NHE  10000
#define NE   800000
#define NI   800000
#define HID  128
#define OUTC 64

// ---------------- device scratch ----------------
__device__ __align__(16) float g_A[NN * HID];
__device__ __align__(16) float g_B[NN * HID];
__device__ __align__(16) float g_X1[NN * HID];
__device__ __align__(16) float g_X2[NN * HID];
__device__ __align__(16) float g_M[NHE * HID];
// packed bf16 split weights: per w, [chunk(2)][kt(4)][n(128)][t(4)] uint4 = (bh_k01, bh_k89, bm_k01, bm_k89)
__device__ __align__(16) uint4 g_Wp[9 * 4096];
__device__ __align__(16) float g_bsum1[HID];
__device__ __align__(16) float g_bsum2[HID];
__device__ __align__(16) float g_Binv[NHE];
__device__ __align__(16) float g_Dinv[NN];

__device__ int g_idx64;
__device__ __align__(16) int g_deg_he[NHE];
__device__ __align__(16) int g_off_he[NHE + 1];
__device__ __align__(16) int g_cur_he[NHE];
__device__ __align__(16) int g_deg_nh[NN];
__device__ __align__(16) int g_off_nh[NN + 1];
__device__ __align__(16) int g_cur_nh[NN];
__device__ __align__(16) int g_deg_nd[NN];
__device__ __align__(16) int g_off_nd[NN + 1];
__device__ __align__(16) int g_cur_nd[NN];
__device__ int g_list_he[NI];
__device__ int g_list_nh[NI];
__device__ int g_list_nd[NE];

__device__ __forceinline__ float leakyf(float x) { return x >= 0.f ? x : 0.01f * x; }
__device__ __forceinline__ int clampi(int v, int hi) { return v < 0 ? 0 : (v >= hi ? hi - 1 : v); }

__device__ __forceinline__ int idxat(const int* __restrict__ a, int pos) {
    return g_idx64 ? a[2 * (long long)pos] : a[pos];
}

__device__ __forceinline__ const float* srcbuf(int id, const float* ext) {
    switch (id) {
        case 0: return g_A;
        case 1: return g_B;
        case 2: return g_X1;
        case 3: return g_X2;
        default: return ext;
    }
}
__device__ __forceinline__ float* dstbuf(int id, float* ext) {
    switch (id) {
        case 0: return g_A;
        case 1: return g_B;
        case 2: return g_X1;
        case 3: return g_X2;
        default: return ext;
    }
}

// pack two floats into bf16x2: lo -> bits[15:0], hi -> bits[31:16]
__device__ __forceinline__ uint32_t packbf(float lo, float hi) {
    uint32_t r;
    asm("cvt.rn.bf16x2.f32 %0, %1, %2;" : "=r"(r) : "f"(hi), "f"(lo));
    return r;
}
__device__ __forceinline__ float bf_lowf(uint32_t u)  { return __uint_as_float(u << 16); }
__device__ __forceinline__ float bf_highf(uint32_t u) { return __uint_as_float(u & 0xffff0000u); }

__device__ __forceinline__ void mma16(float c[4], uint32_t a0, uint32_t a1, uint32_t a2, uint32_t a3,
                                      uint32_t b0, uint32_t b1) {
    asm volatile("mma.sync.aligned.m16n8k16.row.col.f32.bf16.bf16.f32 "
                 "{%0,%1,%2,%3},{%4,%5,%6,%7},{%8,%9},{%0,%1,%2,%3};"
                 : "+f"(c[0]), "+f"(c[1]), "+f"(c[2]), "+f"(c[3])
                 : "r"(a0), "r"(a1), "r"(a2), "r"(a3), "r"(b0), "r"(b1));
}

// ---------------- weight prep: transpose + bf16 hi/mid decompose into packed mma fragments ----
// grid y: 0..8 = weights ; 9 = bias combine row
struct WList {
    const float* a[9]; const float* b[9]; int ncols[9];
    const float* ba1; const float* bb1; const float* ba2; const float* bb2;
};

__global__ void decompose_kernel(WList wl) {
    int w = blockIdx.y;
    int i = blockIdx.x * blockDim.x + threadIdx.x;   // 0..4095
    if (w == 9) {
        if (blockIdx.x == 0 && i < HID) {
            g_bsum1[i] = wl.ba1[i] + wl.bb1[i];
            g_bsum2[i] = wl.ba2[i] + wl.bb2[i];
        }
        return;
    }
    int t = i & 3, n = (i >> 2) & 127, kt = (i >> 9) & 3, ch = i >> 11;
    int NC = wl.ncols[w];
    int kb = ch * 64 + kt * 16 + 2 * t;
    float v0 = 0.f, v1 = 0.f, v2 = 0.f, v3 = 0.f;
    if (n < NC) {
        v0 = wl.a[w][(kb + 0) * NC + n];
        v1 = wl.a[w][(kb + 1) * NC + n];
        v2 = wl.a[w][(kb + 8) * NC + n];
        v3 = wl.a[w][(kb + 9) * NC + n];
        if (wl.b[w]) {
            v0 += wl.b[w][(kb + 0) * NC + n];
            v1 += wl.b[w][(kb + 1) * NC + n];
            v2 += wl.b[w][(kb + 8) * NC + n];
            v3 += wl.b[w][(kb + 9) * NC + n];
        }
    }
    uint32_t h01 = packbf(v0, v1);
    uint32_t h89 = packbf(v2, v3);
    uint32_t m01 = packbf(v0 - bf_lowf(h01), v1 - bf_highf(h01));
    uint32_t m89 = packbf(v2 - bf_lowf(h89), v3 - bf_highf(h89));
    g_Wp[w * 4096 + i] = make_uint4(h01, h89, m01, m89);
}

// ---------------- CSR build (zero + dtype detect fused) ----------------
__global__ void zero_deg_kernel(const int* __restrict__ he) {
    int i = blockIdx.x * blockDim.x + threadIdx.x;
    if (blockIdx.x == 0) {
        __shared__ int any;
        if (threadIdx.x == 0) any = 0;
        __syncthreads();
        if (he[2 * threadIdx.x + 1] != 0) atomicOr(&any, 1);
        __syncthreads();
        if (threadIdx.x == 0) g_idx64 = (any == 0) ? 1 : 0;
    }
    if (i < NHE) g_deg_he[i] = 0;
    if (i < NN) { g_deg_nh[i] = 0; g_deg_nd[i] = 0; }
}

__global__ void count_kernel(const int* __restrict__ he, const int* __restrict__ ed) {
    int i = blockIdx.x * blockDim.x + threadIdx.x;
    if (i < NI) {
        atomicAdd(&g_deg_nh[clampi(idxat(he, i), NN)], 1);
        atomicAdd(&g_deg_he[clampi(idxat(he, NI + i), NHE)], 1);
    }
    if (i < NE) {
        atomicAdd(&g_deg_nd[clampi(idxat(ed, NE + i), NN)], 1);
    }
}

// fast two-level shuffle scan; 3 independent scans, blockIdx.x = which
__global__ void scan_kernel() {
    int which = blockIdx.x;
    const int* __restrict__ deg; int n; int* __restrict__ off; int* __restrict__ cur;
    float* __restrict__ inv;
    if (which == 0)      { deg = g_deg_he; n = NHE; off = g_off_he; cur = g_cur_he; inv = g_Binv; }
    else if (which == 1) { deg = g_deg_nh; n = NN;  off = g_off_nh; cur = g_cur_nh; inv = g_Dinv; }
    else                 { deg = g_deg_nd; n = NN;  off = g_off_nd; cur = g_cur_nd; inv = 0; }

    __shared__ int wsum[32];
    __shared__ int s_tot;
    __shared__ int s_run;
    int tid = threadIdx.x;
    int lane = tid & 31, wid = tid >> 5;
    if (tid == 0) s_run = 0;
    __syncthreads();

    int nt = (n + 4095) / 4096;
    for (int t = 0; t < nt; ++t) {
        int base = t * 4096 + tid * 4;
        int d0 = 0, d1 = 0, d2 = 0, d3 = 0;
        if (base + 3 < n) {
            int4 v = *(const int4*)&deg[base];
            d0 = v.x; d1 = v.y; d2 = v.z; d3 = v.w;
        } else {
            if (base + 0 < n) d0 = deg[base + 0];
            if (base + 1 < n) d1 = deg[base + 1];
            if (base + 2 < n) d2 = deg[base + 2];
            if (base + 3 < n) d3 = deg[base + 3];
        }
        int s = d0 + d1 + d2 + d3;
        int incl = s;
#pragma unroll
        for (int o = 1; o < 32; o <<= 1) {
            int v = __shfl_up_sync(0xFFFFFFFFu, incl, o);
            if (lane >= o) incl += v;
        }
        if (lane == 31) wsum[wid] = incl;
        __syncthreads();
        if (wid == 0) {
            int ws = wsum[lane];
            int wincl = ws;
#pragma unroll
            for (int o = 1; o < 32; o <<= 1) {
                int v = __shfl_up_sync(0xFFFFFFFFu, wincl, o);
                if (lane >= o) wincl += v;
            }
            wsum[lane] = wincl - ws;
            if (lane == 31) s_tot = wincl;
        }
        __syncthreads();
        int excl = s_run + wsum[wid] + (incl - s);
        int o0 = excl, o1 = o0 + d0, o2 = o1 + d1, o3 = o2 + d2;
        if (base + 3 < n) {
            *(int4*)&off[base] = make_int4(o0, o1, o2, o3);
            *(int4*)&cur[base] = make_int4(o0, o1, o2, o3);
            if (inv) {
                float4 f;
                f.x = d0 ? 1.0f / (float)d0 : 0.0f;
                f.y = d1 ? 1.0f / (float)d1 : 0.0f;
                f.z = d2 ? 1.0f / (float)d2 : 0.0f;
                f.w = d3 ? 1.0f / (float)d3 : 0.0f;
                *(float4*)&inv[base] = f;
            }
        } else {
            if (base + 0 < n) { off[base + 0] = o0; cur[base + 0] = o0; if (inv) inv[base + 0] = d0 ? 1.0f / (float)d0 : 0.0f; }
            if (base + 1 < n) { off[base + 1] = o1; cur[base + 1] = o1; if (inv) inv[base + 1] = d1 ? 1.0f / (float)d1 : 0.0f; }
            if (base + 2 < n) { off[base + 2] = o2; cur[base + 2] = o2; if (inv) inv[base + 2] = d2 ? 1.0f / (float)d2 : 0.0f; }
            if (base + 3 < n) { off[base + 3] = o3; cur[base + 3] = o3; if (inv) inv[base + 3] = d3 ? 1.0f / (float)d3 : 0.0f; }
        }
        __syncthreads();
        if (tid == 0) s_run += s_tot;
        __syncthreads();
    }
    if (tid == 0) off[n] = s_run;
}

__global__ void fill_kernel(const int* __restrict__ he, const int* __restrict__ ed) {
    int i = blockIdx.x * blockDim.x + threadIdx.x;
    if (i < NI) {
        int n = clampi(idxat(he, i), NN);
        int h = clampi(idxat(he, NI + i), NHE);
        g_list_he[atomicAdd(&g_cur_he[h], 1)] = n;
        g_list_nh[atomicAdd(&g_cur_nh[n], 1)] = h;
    }
    if (i < NE) {
        int s = clampi(idxat(ed, i), NN);
        int d = clampi(idxat(ed, NE + i), NN);
        g_list_nd[atomicAdd(&g_cur_nd[d], 1)] = s;
    }
}

// ---------------- gather segment-sums (1 warp per output row, 8-deep MLP) ----------------
#define GATHER_BODY(listarr, srcptr) \
    float ax = 0.f, ay = 0.f, az = 0.f, aw = 0.f; \
    int i = beg; \
    for (; i + 8 <= end; i += 8) { \
        int n0 = listarr[i], n1 = listarr[i + 1], n2 = listarr[i + 2], n3 = listarr[i + 3]; \
        int n4 = listarr[i + 4], n5 = listarr[i + 5], n6 = listarr[i + 6], n7 = listarr[i + 7]; \
        float4 v0 = srcptr[n0 * 32 + lane]; \
        float4 v1 = srcptr[n1 * 32 + lane]; \
        float4 v2 = srcptr[n2 * 32 + lane]; \
        float4 v3 = srcptr[n3 * 32 + lane]; \
        float4 v4 = srcptr[n4 * 32 + lane]; \
        float4 v5 = srcptr[n5 * 32 + lane]; \
        float4 v6 = srcptr[n6 * 32 + lane]; \
        float4 v7 = srcptr[n7 * 32 + lane]; \
        ax += ((v0.x + v1.x) + (v2.x + v3.x)) + ((v4.x + v5.x) + (v6.x + v7.x)); \
        ay += ((v0.y + v1.y) + (v2.y + v3.y)) + ((v4.y + v5.y) + (v6.y + v7.y)); \
        az += ((v0.z + v1.z) + (v2.z + v3.z)) + ((v4.z + v5.z) + (v6.z + v7.z)); \
        aw += ((v0.w + v1.w) + (v2.w + v3.w)) + ((v4.w + v5.w) + (v6.w + v7.w)); \
    } \
    for (; i < end; ++i) { \
        int nn_ = listarr[i]; \
        float4 v = srcptr[nn_ * 32 + lane]; \
        ax += v.x; ay += v.y; az += v.z; aw += v.w; \
    }

__global__ void gather_he_kernel() {
    int row = (blockIdx.x * blockDim.x + threadIdx.x) >> 5;
    if (row >= NHE) return;
    int lane = threadIdx.x & 31;
    int beg = g_off_he[row], end = g_off_he[row + 1];
    const float4* src = (const float4*)g_A;
    GATHER_BODY(g_list_he, src)
    float b = g_Binv[row];
    ((float4*)g_M)[row * 32 + lane] = make_float4(ax * b, ay * b, az * b, aw * b);
}

__global__ void gather_node_fuse_kernel(const float4* __restrict__ hcb,
                                        const float4* __restrict__ linb,
                                        int outsel) {
    int row = (blockIdx.x * blockDim.x + threadIdx.x) >> 5;
    if (row >= NN) return;
    int lane = threadIdx.x & 31;
    int beg = g_off_nh[row], end = g_off_nh[row + 1];
    const float4* m = (const float4*)g_M;
    GATHER_BODY(g_list_nh, m)
    float dinv = g_Dinv[row];
    float4 b1 = hcb[lane];
    float4 b2 = linb[lane];
    const float4* linP = (const float4*)g_B;
    float4 l = linP[row * 32 + lane];
    float4 r;
    r.x = leakyf(ax * dinv + b1.x + b2.x + l.x);
    r.y = leakyf(ay * dinv + b1.y + b2.y + l.y);
    r.z = leakyf(az * dinv + b1.z + b2.z + l.z);
    r.w = leakyf(aw * dinv + b1.w + b2.w + l.w);
    ((float4*)dstbuf(outsel, 0))[row * 32 + lane] = r;
}

__global__ void gather_edge_kernel(int srcsel) {
    int row = (blockIdx.x * blockDim.x + threadIdx.x) >> 5;
    if (row >= NN) return;
    int lane = threadIdx.x & 31;
    int beg = g_off_nd[row], end = g_off_nd[row + 1];
    const float4* src = (const float4*)srcbuf(srcsel, 0);
    GATHER_BODY(g_list_nd, src)
    ((float4*)g_A)[row * 32 + lane] = make_float4(ax, ay, az, aw);
}

// ---------------- split-BF16 (3-term) tensor-core GEMM with packed-B fragments ----------------
// NCH=2: C[M x KOUT] = A[M x 128] @ W(widx).
// NCH=4: C = A @ W(widx) + A2(asel2) @ W(widx2)  (K-concat fusion).
// If gridDim.y == 2, blockIdx.y == 1 uses widxB/cselB (independent pair in one launch).
// MODE 0: C = acc ; MODE 1: C = acc + bias_ext ; MODE 5: C = leaky(acc + bsum(bs))
template <int MODE, int NT, int NCH>
__global__ __launch_bounds__(256, 2)
void gemm_bf16(const float* __restrict__ Aext, float* __restrict__ Cext,
               const float* __restrict__ bias_ext, int asel, int asel2, int csel,
               int widx, int widx2, int bs, int M, int widxB, int cselB) {
    constexpr int KOUT = NT * 8;
    if (blockIdx.y == 1) { widx = widxB; csel = cselB; }
    const float* A = srcbuf(asel, Aext);
    const float* A2 = (NCH == 4) ? srcbuf(asel2, 0) : A;
    float* C = dstbuf(csel, Cext);

    extern __shared__ float sm[];
    float* As = sm;                           // [128][68] fp32
    uint4* Bsu = (uint4*)(sm + 128 * 68);     // [4 kt][128 n][4 t] packed fragments

    int tid = threadIdx.x;
    int lane = tid & 31, warp = tid >> 5;
    int g = lane >> 2, t = lane & 3;
    int brow = blockIdx.x * 128;
    int wr = warp * 16;

    float c[NT][4];
#pragma unroll
    for (int nt = 0; nt < NT; ++nt)
#pragma unroll
        for (int j = 0; j < 4; ++j) c[nt][j] = 0.f;

#pragma unroll
    for (int chunk = 0; chunk < NCH; ++chunk) {
        const float* Asrc = (NCH == 4 && chunk >= 2) ? A2 : A;
        int k0 = (chunk & 1) * 64;
        int w = (NCH == 4 && chunk >= 2) ? widx2 : widx;
        if (chunk) __syncthreads();
        // stage A chunk [128 rows][64 k] fp32
#pragma unroll
        for (int p = 0; p < 8; ++p) {
            int idx = p * 256 + tid;
            int r = idx >> 4, c4 = (idx & 15) * 4;
            int gr = brow + r;
            float4 v = make_float4(0.f, 0.f, 0.f, 0.f);
            if (gr < M) v = *(const float4*)&Asrc[(size_t)gr * 128 + k0 + c4];
            *(float4*)&As[r * 68 + c4] = v;
        }
        // stage packed B fragments: 2048 uint4 straight copy
        const uint4* Wp = g_Wp + w * 4096 + (chunk & 1) * 2048;
#pragma unroll
        for (int p = 0; p < 8; ++p) {
            int idx = p * 256 + tid;
            Bsu[idx] = Wp[idx];
        }
        __syncthreads();

#pragma unroll
        for (int kt = 0; kt < 4; ++kt) {
            int kk = kt * 16;
            int b0 = (wr + g) * 68 + kk + 2 * t;
            int b1 = (wr + g + 8) * 68 + kk + 2 * t;
            float a00 = As[b0],     a01 = As[b0 + 1];
            float a02 = As[b0 + 8], a03 = As[b0 + 9];
            float a10 = As[b1],     a11 = As[b1 + 1];
            float a12 = As[b1 + 8], a13 = As[b1 + 9];
            uint32_t A0h = packbf(a00, a01);
            uint32_t A1h = packbf(a10, a11);
            uint32_t A2h = packbf(a02, a03);
            uint32_t A3h = packbf(a12, a13);
            uint32_t A0m = packbf(a00 - bf_lowf(A0h), a01 - bf_highf(A0h));
            uint32_t A1m = packbf(a10 - bf_lowf(A1h), a11 - bf_highf(A1h));
            uint32_t A2m = packbf(a02 - bf_lowf(A2h), a03 - bf_highf(A2h));
            uint32_t A3m = packbf(a12 - bf_lowf(A3h), a13 - bf_highf(A3h));
#pragma unroll
            for (int nt = 0; nt < NT; ++nt) {
                uint4 b = Bsu[kt * 512 + (nt * 8 + g) * 4 + t];
                mma16(c[nt], A0h, A1h, A2h, A3h, b.x, b.y);   // Ah * Bh
                mma16(c[nt], A0m, A1m, A2m, A3m, b.x, b.y);   // Am * Bh
                mma16(c[nt], A0h, A1h, A2h, A3h, b.z, b.w);   // Ah * Bm
            }
        }
    }

    // epilogue (fragment layout identical to m16n8k8)
    const float* bsum = bs ? g_bsum2 : g_bsum1;
    int r0 = brow + wr + g;
    int r1 = r0 + 8;
#pragma unroll
    for (int nt = 0; nt < NT; ++nt) {
        int col = nt * 8 + 2 * t;
        if (r0 < M) {
            float v0 = c[nt][0], v1 = c[nt][1];
            if (MODE == 1) { v0 += bias_ext[col]; v1 += bias_ext[col + 1]; }
            if (MODE == 5) {
                v0 = leakyf(v0 + bsum[col]);
                v1 = leakyf(v1 + bsum[col + 1]);
            }
            *(float2*)&C[(size_t)r0 * KOUT + col] = make_float2(v0, v1);
        }
        if (r1 < M) {
            float v2 = c[nt][2], v3 = c[nt][3];
            if (MODE == 1) { v2 += bias_ext[col]; v3 += bias_ext[col + 1]; }
            if (MODE == 5) {
                v2 = leakyf(v2 + bsum[col]);
                v3 = leakyf(v3 + bsum[col + 1]);
            }
            *(float2*)&C[(size_t)r1 * KOUT + col] = make_float2(v2, v3);
        }
    }
}

// ---------------- launch ----------------
extern "C" void kernel_launch(void* const* d_in, const int* in_sizes, int n_in,
                              void* d_out, int out_size) {
    const float* X     = (const float*)d_in[0];
    const int* eidx    = (const int*)d_in[1];
    const int* hidx    = (const int*)d_in[2];
    const float* hc1w  = (const float*)d_in[3];
    const float* hc1b  = (const float*)d_in[4];
    const float* lin1w = (const float*)d_in[5];
    const float* lin1b = (const float*)d_in[6];
    const float* hc2w  = (const float*)d_in[7];
    const float* hc2b  = (const float*)d_in[8];
    const float* lin2w = (const float*)d_in[9];
    const float* lin2b = (const float*)d_in[10];
    const float* c1wrel  = (const float*)d_in[11];
    const float* c1brel  = (const float*)d_in[12];
    const float* c1wroot = (const float*)d_in[13];
    const float* glin1w  = (const float*)d_in[14];
    const float* glin1b  = (const float*)d_in[15];
    const float* c2wrel  = (const float*)d_in[16];
    const float* c2brel  = (const float*)d_in[17];
    const float* c2wroot = (const float*)d_in[18];
    const float* glin2w  = (const float*)d_in[19];
    const float* glin2b  = (const float*)d_in[20];
    const float* fcw = (const float*)d_in[21];
    const float* fcb = (const float*)d_in[22];

    const size_t NX = (size_t)NN * HID;
    const size_t NYsz = (size_t)NN * OUTC;
    bool full_out = ((size_t)out_size >= NX + NYsz);
    float* outX = (float*)d_out;
    float* outY = full_out ? (outX + NX) : (float*)d_out;
    int final_csel = full_out ? -1 : 3;
    int fc_asel    = full_out ? -1 : 3;
    const float* fc_Aext = full_out ? outX : (const float*)0;

    const int TPB = 256;
    const int SMEMSZ = 128 * 68 * 4 + 2048 * 16;    // 34816 + 32768 = 67584 B
    int gG = (NN + 127) / 128;
    int gbE   = (NE + TPB - 1) / TPB;
    int gbHEw = (NHE * 32 + TPB - 1) / TPB;
    int gbNw  = (NN * 32 + TPB - 1) / TPB;

    cudaFuncSetAttribute((const void*)gemm_bf16<0, 16, 2>, cudaFuncAttributeMaxDynamicSharedMemorySize, SMEMSZ);
    cudaFuncSetAttribute((const void*)gemm_bf16<5, 16, 4>, cudaFuncAttributeMaxDynamicSharedMemorySize, SMEMSZ);
    cudaFuncSetAttribute((const void*)gemm_bf16<1, 8, 2>,  cudaFuncAttributeMaxDynamicSharedMemorySize, SMEMSZ);

    // ---- weight prep (bias combine fused as grid row 9) ----
    WList wl;
    wl.a[0] = hc1w;    wl.b[0] = 0;      wl.ncols[0] = 128;
    wl.a[1] = lin1w;   wl.b[1] = 0;      wl.ncols[1] = 128;
    wl.a[2] = hc2w;    wl.b[2] = 0;      wl.ncols[2] = 128;
    wl.a[3] = lin2w;   wl.b[3] = 0;      wl.ncols[3] = 128;
    wl.a[4] = c1wrel;  wl.b[4] = 0;      wl.ncols[4] = 128;
    wl.a[5] = c1wroot; wl.b[5] = glin1w; wl.ncols[5] = 128;
    wl.a[6] = c2wrel;  wl.b[6] = 0;      wl.ncols[6] = 128;
    wl.a[7] = c2wroot; wl.b[7] = glin2w; wl.ncols[7] = 128;
    wl.a[8] = fcw;     wl.b[8] = 0;      wl.ncols[8] = 64;
    wl.ba1 = c1brel; wl.bb1 = glin1b; wl.ba2 = c2brel; wl.bb2 = glin2b;
    decompose_kernel<<<dim3(16, 10), TPB>>>(wl);

    // ---- CSR build (detect fused into zero) ----
    zero_deg_kernel<<<(NN + TPB - 1) / TPB, TPB>>>(hidx);
    count_kernel<<<gbE, TPB>>>(hidx, eidx);
    scan_kernel<<<3, 1024>>>();
    fill_kernel<<<gbE, TPB>>>(hidx, eidx);

    // ---- layer 1 (hypergraph): paired GEMMs in one launch ----
    gemm_bf16<0, 16, 2><<<dim3(gG, 2), TPB, SMEMSZ>>>(X, 0, 0, -1, -1, 0, 0, 0, 0, NN, 1, 1);  // g_A=X@hc1w ; g_B=X@lin1w
    gather_he_kernel<<<gbHEw, TPB>>>();
    gather_node_fuse_kernel<<<gbNw, TPB>>>((const float4*)hc1b, (const float4*)lin1b, 2);

    // ---- layer 2 (hypergraph) ----
    gemm_bf16<0, 16, 2><<<dim3(gG, 2), TPB, SMEMSZ>>>(0, 0, 0, 2, -1, 0, 2, 0, 0, NN, 3, 1);   // g_A=g_X1@hc2w ; g_B=g_X1@lin2w
    gather_he_kernel<<<gbHEw, TPB>>>();
    gather_node_fuse_kernel<<<gbNw, TPB>>>((const float4*)hc2b, (const float4*)lin2b, 3);

    // ---- layer 3 (graph): K-concat fused GEMM ----
    gather_edge_kernel<<<gbNw, TPB>>>(3);                                            // g_A = segsum(g_X2)
    gemm_bf16<5, 16, 4><<<gG, TPB, SMEMSZ>>>(0, 0, 0, 0, 3, 2, 4, 5, 0, NN, 4, 2);   // g_X1 = leaky(g_A@c1wrel + g_X2@Wc1 + bsum1)

    // ---- layer 4 (graph) ----
    gather_edge_kernel<<<gbNw, TPB>>>(2);                                            // g_A = segsum(g_X1)
    gemm_bf16<5, 16, 4><<<gG, TPB, SMEMSZ>>>(0, outX, 0, 0, 2, final_csel, 6, 7, 1, NN, 6, final_csel);  // X4

    // ---- fc head ----
    gemm_bf16<1, 8, 2><<<gG, TPB, SMEMSZ>>>(fc_Aext, outY, fcb, fc_asel, -1, -1, 8, 8, 0, NN, 8, -1);
}

// round 17
// speedup vs baseline: 1.7994x; 1.0069x over previous
#include <cuda_runtime.h>
#include <cstdint>

#define NN   50000
#define NHE  10000
#define NE   800000
#define NI   800000
#define HID  128
#define OUTC 64

// ---------------- device scratch ----------------
__device__ __align__(16) float g_A[NN * HID];
__device__ __align__(16) float g_X1[NN * HID];
__device__ __align__(16) float g_X2[NN * HID];
__device__ __align__(16) float g_M[NHE * HID];
// packed bf16 split weights: per w, [chunk(2)][kt(4)][n(128)][t(4)] uint4 = (bh_k01, bh_k89, bm_k01, bm_k89)
__device__ __align__(16) uint4 g_Wp[9 * 4096];
__device__ __align__(16) float g_bsum[4 * HID];   // 0:hc1b+lin1b 1:hc2b+lin2b 2:c1brel+glin1b 3:c2brel+glin2b
__device__ __align__(16) float g_Binv[NHE];
__device__ __align__(16) float g_Dinv[NN];

__device__ int g_idx64;
__device__ int g_tot[3];
__device__ __align__(16) int g_deg_he[NHE];
__device__ __align__(16) int g_off_he[NHE];
__device__ __align__(16) int g_cur_he[NHE];
__device__ __align__(16) int g_deg_nh[NN];
__device__ __align__(16) int g_off_nh[NN];
__device__ __align__(16) int g_cur_nh[NN];
__device__ __align__(16) int g_deg_nd[NN];
__device__ __align__(16) int g_off_nd[NN];
__device__ __align__(16) int g_cur_nd[NN];
__device__ int g_list_he[NI];
__device__ int g_list_nh[NI];
__device__ int g_list_nd[NE];

__device__ __forceinline__ float leakyf(float x) { return x >= 0.f ? x : 0.01f * x; }
__device__ __forceinline__ int clampi(int v, int hi) { return v < 0 ? 0 : (v >= hi ? hi - 1 : v); }

__device__ __forceinline__ int idxat(const int* __restrict__ a, int pos) {
    return g_idx64 ? a[2 * (long long)pos] : a[pos];
}

__device__ __forceinline__ const float* srcbuf(int id, const float* ext) {
    switch (id) {
        case 0: return g_A;
        case 2: return g_X1;
        case 3: return g_X2;
        default: return ext;
    }
}
__device__ __forceinline__ float* dstbuf(int id, float* ext) {
    switch (id) {
        case 0: return g_A;
        case 2: return g_X1;
        case 3: return g_X2;
        default: return ext;
    }
}

// pack two floats into bf16x2: lo -> bits[15:0], hi -> bits[31:16]
__device__ __forceinline__ uint32_t packbf(float lo, float hi) {
    uint32_t r;
    asm("cvt.rn.bf16x2.f32 %0, %1, %2;" : "=r"(r) : "f"(hi), "f"(lo));
    return r;
}
__device__ __forceinline__ float bf_lowf(uint32_t u)  { return __uint_as_float(u << 16); }
__device__ __forceinline__ float bf_highf(uint32_t u) { return __uint_as_float(u & 0xffff0000u); }

__device__ __forceinline__ void mma16(float c[4], uint32_t a0, uint32_t a1, uint32_t a2, uint32_t a3,
                                      uint32_t b0, uint32_t b1) {
    asm volatile("mma.sync.aligned.m16n8k16.row.col.f32.bf16.bf16.f32 "
                 "{%0,%1,%2,%3},{%4,%5,%6,%7},{%8,%9},{%0,%1,%2,%3};"
                 : "+f"(c[0]), "+f"(c[1]), "+f"(c[2]), "+f"(c[3])
                 : "r"(a0), "r"(a1), "r"(a2), "r"(a3), "r"(b0), "r"(b1));
}

// ---------------- weight prep: transpose + bf16 hi/mid decompose into packed mma fragments ----
// grid y: 0..8 = weights ; 9 = bias combine row
struct WList {
    const float* a[9]; const float* b[9]; int ncols[9];
    const float* bp[8];   // 4 pairs -> g_bsum rows
};

__global__ void decompose_kernel(WList wl) {
    int w = blockIdx.y;
    int i = blockIdx.x * blockDim.x + threadIdx.x;   // 0..4095
    if (w == 9) {
        if (blockIdx.x == 0 && i < HID) {
#pragma unroll
            for (int j = 0; j < 4; ++j)
                g_bsum[j * HID + i] = wl.bp[2 * j][i] + wl.bp[2 * j + 1][i];
        }
        return;
    }
    int t = i & 3, n = (i >> 2) & 127, kt = (i >> 9) & 3, ch = i >> 11;
    int NC = wl.ncols[w];
    int kb = ch * 64 + kt * 16 + 2 * t;
    float v0 = 0.f, v1 = 0.f, v2 = 0.f, v3 = 0.f;
    if (n < NC) {
        v0 = wl.a[w][(kb + 0) * NC + n];
        v1 = wl.a[w][(kb + 1) * NC + n];
        v2 = wl.a[w][(kb + 8) * NC + n];
        v3 = wl.a[w][(kb + 9) * NC + n];
        if (wl.b[w]) {
            v0 += wl.b[w][(kb + 0) * NC + n];
            v1 += wl.b[w][(kb + 1) * NC + n];
            v2 += wl.b[w][(kb + 8) * NC + n];
            v3 += wl.b[w][(kb + 9) * NC + n];
        }
    }
    uint32_t h01 = packbf(v0, v1);
    uint32_t h89 = packbf(v2, v3);
    uint32_t m01 = packbf(v0 - bf_lowf(h01), v1 - bf_highf(h01));
    uint32_t m89 = packbf(v2 - bf_lowf(h89), v3 - bf_highf(h89));
    g_Wp[w * 4096 + i] = make_uint4(h01, h89, m01, m89);
}

// ---------------- CSR build (zero + dtype detect fused) ----------------
__global__ void zero_deg_kernel(const int* __restrict__ he) {
    int i = blockIdx.x * blockDim.x + threadIdx.x;
    if (blockIdx.x == 0) {
        __shared__ int any;
        if (threadIdx.x == 0) any = 0;
        __syncthreads();
        if (he[2 * threadIdx.x + 1] != 0) atomicOr(&any, 1);
        __syncthreads();
        if (threadIdx.x == 0) {
            g_idx64 = (any == 0) ? 1 : 0;
            g_tot[0] = 0; g_tot[1] = 0; g_tot[2] = 0;
        }
    }
    if (i < NHE) g_deg_he[i] = 0;
    if (i < NN) { g_deg_nh[i] = 0; g_deg_nd[i] = 0; }
}

__global__ void count_kernel(const int* __restrict__ he, const int* __restrict__ ed) {
    int i = blockIdx.x * blockDim.x + threadIdx.x;
    if (i < NI) {
        atomicAdd(&g_deg_nh[clampi(idxat(he, i), NN)], 1);
        atomicAdd(&g_deg_he[clampi(idxat(he, NI + i), NHE)], 1);
    }
    if (i < NE) {
        atomicAdd(&g_deg_nd[clampi(idxat(ed, NE + i), NN)], 1);
    }
}

// warp-aggregated range allocator: off[i] = disjoint range of size deg[i].
// (Order is atomic-nondeterministic but any disjoint allocation is valid;
//  within-row list order is already atomic-nondeterministic via fill_kernel.)
__global__ void alloc_kernel() {
    int i = blockIdx.x * blockDim.x + threadIdx.x;
    int lane = threadIdx.x & 31;

#define ALLOC_ONE(deg_arr, off_arr, cur_arr, inv_arr, n, slot)                 \
    {                                                                          \
        int d = (i < n) ? deg_arr[i] : 0;                                      \
        int incl = d;                                                          \
        _Pragma("unroll")                                                      \
        for (int o = 1; o < 32; o <<= 1) {                                     \
            int v = __shfl_up_sync(0xFFFFFFFFu, incl, o);                      \
            if (lane >= o) incl += v;                                          \
        }                                                                      \
        int tot = __shfl_sync(0xFFFFFFFFu, incl, 31);                          \
        int base = 0;                                                          \
        if (lane == 31 && tot > 0) base = atomicAdd(&g_tot[slot], tot);        \
        base = __shfl_sync(0xFFFFFFFFu, base, 31);                             \
        if (i < n) {                                                           \
            int o = base + incl - d;                                           \
            off_arr[i] = o; cur_arr[i] = o;                                    \
            if (inv_arr) ((float*)inv_arr)[i] = d ? 1.0f / (float)d : 0.0f;    \
        }                                                                      \
    }

    ALLOC_ONE(g_deg_he, g_off_he, g_cur_he, g_Binv, NHE, 0)
    ALLOC_ONE(g_deg_nh, g_off_nh, g_cur_nh, g_Dinv, NN, 1)
    ALLOC_ONE(g_deg_nd, g_off_nd, g_cur_nd, (float*)0, NN, 2)
#undef ALLOC_ONE
}

__global__ void fill_kernel(const int* __restrict__ he, const int* __restrict__ ed) {
    int i = blockIdx.x * blockDim.x + threadIdx.x;
    if (i < NI) {
        int n = clampi(idxat(he, i), NN);
        int h = clampi(idxat(he, NI + i), NHE);
        g_list_he[atomicAdd(&g_cur_he[h], 1)] = n;
        g_list_nh[atomicAdd(&g_cur_nh[n], 1)] = h;
    }
    if (i < NE) {
        int s = clampi(idxat(ed, i), NN);
        int d = clampi(idxat(ed, NE + i), NN);
        g_list_nd[atomicAdd(&g_cur_nd[d], 1)] = s;
    }
}

// ---------------- gather segment-sums (1 warp per output row, 8-deep MLP) ----------------
#define GATHER_BODY(listarr, srcptr) \
    float ax = 0.f, ay = 0.f, az = 0.f, aw = 0.f; \
    int i = beg; \
    for (; i + 8 <= end; i += 8) { \
        int n0 = listarr[i], n1 = listarr[i + 1], n2 = listarr[i + 2], n3 = listarr[i + 3]; \
        int n4 = listarr[i + 4], n5 = listarr[i + 5], n6 = listarr[i + 6], n7 = listarr[i + 7]; \
        float4 v0 = srcptr[n0 * 32 + lane]; \
        float4 v1 = srcptr[n1 * 32 + lane]; \
        float4 v2 = srcptr[n2 * 32 + lane]; \
        float4 v3 = srcptr[n3 * 32 + lane]; \
        float4 v4 = srcptr[n4 * 32 + lane]; \
        float4 v5 = srcptr[n5 * 32 + lane]; \
        float4 v6 = srcptr[n6 * 32 + lane]; \
        float4 v7 = srcptr[n7 * 32 + lane]; \
        ax += ((v0.x + v1.x) + (v2.x + v3.x)) + ((v4.x + v5.x) + (v6.x + v7.x)); \
        ay += ((v0.y + v1.y) + (v2.y + v3.y)) + ((v4.y + v5.y) + (v6.y + v7.y)); \
        az += ((v0.z + v1.z) + (v2.z + v3.z)) + ((v4.z + v5.z) + (v6.z + v7.z)); \
        aw += ((v0.w + v1.w) + (v2.w + v3.w)) + ((v4.w + v5.w) + (v6.w + v7.w)); \
    } \
    for (; i < end; ++i) { \
        int nn_ = listarr[i]; \
        float4 v = srcptr[nn_ * 32 + lane]; \
        ax += v.x; ay += v.y; az += v.z; aw += v.w; \
    }

// node rows -> hyperedge rows (g_M), scaled by Binv. srcsel<0: external (X).
__global__ void gather_he_kernel(const float4* __restrict__ ext, int srcsel) {
    int row = (blockIdx.x * blockDim.x + threadIdx.x) >> 5;
    if (row >= NHE) return;
    int lane = threadIdx.x & 31;
    int beg = g_off_he[row];
    int end = beg + g_deg_he[row];
    const float4* src = (srcsel >= 0) ? (const float4*)srcbuf(srcsel, 0) : ext;
    GATHER_BODY(g_list_he, src)
    float b = g_Binv[row];
    ((float4*)g_M)[row * 32 + lane] = make_float4(ax * b, ay * b, az * b, aw * b);
}

// hyperedge rows (g_M) -> node rows (g_A), scaled by Dinv (plain; lin/bias/leaky in GEMM)
__global__ void gather_node_kernel() {
    int row = (blockIdx.x * blockDim.x + threadIdx.x) >> 5;
    if (row >= NN) return;
    int lane = threadIdx.x & 31;
    int beg = g_off_nh[row];
    int end = beg + g_deg_nh[row];
    const float4* m = (const float4*)g_M;
    GATHER_BODY(g_list_nh, m)
    float dinv = g_Dinv[row];
    ((float4*)g_A)[row * 32 + lane] = make_float4(ax * dinv, ay * dinv, az * dinv, aw * dinv);
}

__global__ void gather_edge_kernel(int srcsel) {
    int row = (blockIdx.x * blockDim.x + threadIdx.x) >> 5;
    if (row >= NN) return;
    int lane = threadIdx.x & 31;
    int beg = g_off_nd[row];
    int end = beg + g_deg_nd[row];
    const float4* src = (const float4*)srcbuf(srcsel, 0);
    GATHER_BODY(g_list_nd, src)
    ((float4*)g_A)[row * 32 + lane] = make_float4(ax, ay, az, aw);
}

// ---------------- split-BF16 (3-term) tensor-core GEMM with packed-B fragments ----------------
// NCH=2: C[M x KOUT] = A[M x 128] @ W(widx).
// NCH=4: C = A @ W(widx) + A2 @ W(widx2)  (K-concat fusion).
// MODE 1: C = acc + bias_ext ; MODE 5: C = leaky(acc + g_bsum[bs])
template <int MODE, int NT, int NCH>
__global__ __launch_bounds__(256, 2)
void gemm_bf16(const float* __restrict__ Aext, const float* __restrict__ Aext2,
               float* __restrict__ Cext, const float* __restrict__ bias_ext,
               int asel, int asel2, int csel, int widx, int widx2, int bs, int M) {
    constexpr int KOUT = NT * 8;
    const float* A = srcbuf(asel, Aext);
    const float* A2 = (NCH == 4) ? srcbuf(asel2, Aext2) : A;
    float* C = dstbuf(csel, Cext);

    extern __shared__ float sm[];
    float* As = sm;                           // [128][68] fp32
    uint4* Bsu = (uint4*)(sm + 128 * 68);     // [4 kt][128 n][4 t] packed fragments

    int tid = threadIdx.x;
    int lane = tid & 31, warp = tid >> 5;
    int g = lane >> 2, t = lane & 3;
    int brow = blockIdx.x * 128;
    int wr = warp * 16;

    float c[NT][4];
#pragma unroll
    for (int nt = 0; nt < NT; ++nt)
#pragma unroll
        for (int j = 0; j < 4; ++j) c[nt][j] = 0.f;

#pragma unroll
    for (int chunk = 0; chunk < NCH; ++chunk) {
        const float* Asrc = (NCH == 4 && chunk >= 2) ? A2 : A;
        int k0 = (chunk & 1) * 64;
        int w = (NCH == 4 && chunk >= 2) ? widx2 : widx;
        if (chunk) __syncthreads();
        // stage A chunk [128 rows][64 k] fp32
#pragma unroll
        for (int p = 0; p < 8; ++p) {
            int idx = p * 256 + tid;
            int r = idx >> 4, c4 = (idx & 15) * 4;
            int gr = brow + r;
            float4 v = make_float4(0.f, 0.f, 0.f, 0.f);
            if (gr < M) v = *(const float4*)&Asrc[(size_t)gr * 128 + k0 + c4];
            *(float4*)&As[r * 68 + c4] = v;
        }
        // stage packed B fragments: 2048 uint4 straight copy
        const uint4* Wp = g_Wp + w * 4096 + (chunk & 1) * 2048;
#pragma unroll
        for (int p = 0; p < 8; ++p) {
            int idx = p * 256 + tid;
            Bsu[idx] = Wp[idx];
        }
        __syncthreads();

#pragma unroll
        for (int kt = 0; kt < 4; ++kt) {
            int kk = kt * 16;
            int b0 = (wr + g) * 68 + kk + 2 * t;
            int b1 = (wr + g + 8) * 68 + kk + 2 * t;
            float a00 = As[b0],     a01 = As[b0 + 1];
            float a02 = As[b0 + 8], a03 = As[b0 + 9];
            float a10 = As[b1],     a11 = As[b1 + 1];
            float a12 = As[b1 + 8], a13 = As[b1 + 9];
            uint32_t A0h = packbf(a00, a01);
            uint32_t A1h = packbf(a10, a11);
            uint32_t A2h = packbf(a02, a03);
            uint32_t A3h = packbf(a12, a13);
            uint32_t A0m = packbf(a00 - bf_lowf(A0h), a01 - bf_highf(A0h));
            uint32_t A1m = packbf(a10 - bf_lowf(A1h), a11 - bf_highf(A1h));
            uint32_t A2m = packbf(a02 - bf_lowf(A2h), a03 - bf_highf(A2h));
            uint32_t A3m = packbf(a12 - bf_lowf(A3h), a13 - bf_highf(A3h));
#pragma unroll
            for (int nt = 0; nt < NT; ++nt) {
                uint4 b = Bsu[kt * 512 + (nt * 8 + g) * 4 + t];
                mma16(c[nt], A0h, A1h, A2h, A3h, b.x, b.y);   // Ah * Bh
                mma16(c[nt], A0m, A1m, A2m, A3m, b.x, b.y);   // Am * Bh
                mma16(c[nt], A0h, A1h, A2h, A3h, b.z, b.w);   // Ah * Bm
            }
        }
    }

    // epilogue
    const float* bsum = g_bsum + bs * HID;
    int r0 = brow + wr + g;
    int r1 = r0 + 8;
#pragma unroll
    for (int nt = 0; nt < NT; ++nt) {
        int col = nt * 8 + 2 * t;
        if (r0 < M) {
            float v0 = c[nt][0], v1 = c[nt][1];
            if (MODE == 1) { v0 += bias_ext[col]; v1 += bias_ext[col + 1]; }
            if (MODE == 5) {
                v0 = leakyf(v0 + bsum[col]);
                v1 = leakyf(v1 + bsum[col + 1]);
            }
            *(float2*)&C[(size_t)r0 * KOUT + col] = make_float2(v0, v1);
        }
        if (r1 < M) {
            float v2 = c[nt][2], v3 = c[nt][3];
            if (MODE == 1) { v2 += bias_ext[col]; v3 += bias_ext[col + 1]; }
            if (MODE == 5) {
                v2 = leakyf(v2 + bsum[col]);
                v3 = leakyf(v3 + bsum[col + 1]);
            }
            *(float2*)&C[(size_t)r1 * KOUT + col] = make_float2(v2, v3);
        }
    }
}

// ---------------- launch ----------------
extern "C" void kernel_launch(void* const* d_in, const int* in_sizes, int n_in,
                              void* d_out, int out_size) {
    const float* X     = (const float*)d_in[0];
    const int* eidx    = (const int*)d_in[1];
    const int* hidx    = (const int*)d_in[2];
    const float* hc1w  = (const float*)d_in[3];
    const float* hc1b  = (const float*)d_in[4];
    const float* lin1w = (const float*)d_in[5];
    const float* lin1b = (const float*)d_in[6];
    const float* hc2w  = (const float*)d_in[7];
    const float* hc2b  = (const float*)d_in[8];
    const float* lin2w = (const float*)d_in[9];
    const float* lin2b = (const float*)d_in[10];
    const float* c1wrel  = (const float*)d_in[11];
    const float* c1brel  = (const float*)d_in[12];
    const float* c1wroot = (const float*)d_in[13];
    const float* glin1w  = (const float*)d_in[14];
    const float* glin1b  = (const float*)d_in[15];
    const float* c2wrel  = (const float*)d_in[16];
    const float* c2brel  = (const float*)d_in[17];
    const float* c2wroot = (const float*)d_in[18];
    const float* glin2w  = (const float*)d_in[19];
    const float* glin2b  = (const float*)d_in[20];
    const float* fcw = (const float*)d_in[21];
    const float* fcb = (const float*)d_in[22];

    const size_t NX = (size_t)NN * HID;
    const size_t NYsz = (size_t)NN * OUTC;
    bool full_out = ((size_t)out_size >= NX + NYsz);
    float* outX = (float*)d_out;
    float* outY = full_out ? (outX + NX) : (float*)d_out;
    int final_csel = full_out ? -1 : 3;
    int fc_asel    = full_out ? -1 : 3;
    const float* fc_Aext = full_out ? outX : (const float*)0;

    const int TPB = 256;
    const int SMEMSZ = 128 * 68 * 4 + 2048 * 16;    // 67584 B
    int gG = (NN + 127) / 128;
    int gbE   = (NE + TPB - 1) / TPB;
    int gbHEw = (NHE * 32 + TPB - 1) / TPB;
    int gbNw  = (NN * 32 + TPB - 1) / TPB;

    cudaFuncSetAttribute((const void*)gemm_bf16<5, 16, 4>, cudaFuncAttributeMaxDynamicSharedMemorySize, SMEMSZ);
    cudaFuncSetAttribute((const void*)gemm_bf16<1, 8, 2>,  cudaFuncAttributeMaxDynamicSharedMemorySize, SMEMSZ);

    // ---- weight prep (bias combine fused as grid row 9) ----
    WList wl;
    wl.a[0] = hc1w;    wl.b[0] = 0;      wl.ncols[0] = 128;
    wl.a[1] = lin1w;   wl.b[1] = 0;      wl.ncols[1] = 128;
    wl.a[2] = hc2w;    wl.b[2] = 0;      wl.ncols[2] = 128;
    wl.a[3] = lin2w;   wl.b[3] = 0;      wl.ncols[3] = 128;
    wl.a[4] = c1wrel;  wl.b[4] = 0;      wl.ncols[4] = 128;
    wl.a[5] = c1wroot; wl.b[5] = glin1w; wl.ncols[5] = 128;
    wl.a[6] = c2wrel;  wl.b[6] = 0;      wl.ncols[6] = 128;
    wl.a[7] = c2wroot; wl.b[7] = glin2w; wl.ncols[7] = 128;
    wl.a[8] = fcw;     wl.b[8] = 0;      wl.ncols[8] = 64;
    wl.bp[0] = hc1b;   wl.bp[1] = lin1b;
    wl.bp[2] = hc2b;   wl.bp[3] = lin2b;
    wl.bp[4] = c1brel; wl.bp[5] = glin1b;
    wl.bp[6] = c2brel; wl.bp[7] = glin2b;
    decompose_kernel<<<dim3(16, 10), TPB>>>(wl);

    // ---- CSR build ----
    zero_deg_kernel<<<(NN + TPB - 1) / TPB, TPB>>>(hidx);
    count_kernel<<<gbE, TPB>>>(hidx, eidx);
    alloc_kernel<<<(NN + TPB - 1) / TPB, TPB>>>();
    fill_kernel<<<gbE, TPB>>>(hidx, eidx);

    // ---- layer 1 (hypergraph, gather-first) ----
    gather_he_kernel<<<gbHEw, TPB>>>((const float4*)X, -1);          // g_M = Binv * H^T X
    gather_node_kernel<<<gbNw, TPB>>>();                             // g_A = Dinv * H g_M
    gemm_bf16<5, 16, 4><<<gG, TPB, SMEMSZ>>>(0, X, 0, 0, 0, -1, 2, 0, 1, 0, NN);   // g_X1 = leaky(g_A@hc1w + X@lin1w + b0)

    // ---- layer 2 (hypergraph) ----
    gather_he_kernel<<<gbHEw, TPB>>>(0, 2);                          // g_M = Binv * H^T g_X1
    gather_node_kernel<<<gbNw, TPB>>>();                             // g_A = Dinv * H g_M
    gemm_bf16<5, 16, 4><<<gG, TPB, SMEMSZ>>>(0, 0, 0, 0, 0, 2, 3, 2, 3, 1, NN);    // g_X2 = leaky(g_A@hc2w + g_X1@lin2w + b1)

    // ---- layer 3 (graph) ----
    gather_edge_kernel<<<gbNw, TPB>>>(3);                            // g_A = segsum(g_X2)
    gemm_bf16<5, 16, 4><<<gG, TPB, SMEMSZ>>>(0, 0, 0, 0, 0, 3, 2, 4, 5, 2, NN);    // g_X1 = leaky(g_A@c1wrel + g_X2@Wc1 + b2)

    // ---- layer 4 (graph) ----
    gather_edge_kernel<<<gbNw, TPB>>>(2);                            // g_A = segsum(g_X1)
    gemm_bf16<5, 16, 4><<<gG, TPB, SMEMSZ>>>(0, 0, outX, 0, 0, 2, final_csel, 6, 7, 3, NN);  // X4

    // ---- fc head ----
    gemm_bf16<1, 8, 2><<<gG, TPB, SMEMSZ>>>(fc_Aext, 0, outY, fcb, fc_asel, -1, -1, 8, 8, 0, NN);
}